// round 3
// baseline (speedup 1.0000x reference)
#include <cuda_runtime.h>
#include <math.h>

// Problem-fixed dimensions
#define NMAX 50000
#define EMAX 800000
#define BMAX 128

// ---------------- scratch (static device globals; no allocation) ----------------
__device__ float  d_XH  [NMAX * 128];     // current layer's x @ W
__device__ float  d_H1  [NMAX * 128];     // layer-1 output (relu)
__device__ float  d_OUT2[NMAX * 32];      // layer-2 output (head-mean)
__device__ float4 d_ASRC[NMAX];           // per-node attention dots (4 heads)
__device__ float4 d_ADST[NMAX];
__device__ int    d_deg   [NMAX];
__device__ int    d_rowptr[NMAX + 1];
__device__ int    d_cursor[NMAX];
__device__ int    d_col   [EMAX + NMAX];  // CSR by dst: src node ids (incl. self loops)
__device__ float  d_gsum  [BMAX * 32];
__device__ int    d_cnt   [BMAX];

// ---------------- init ----------------
__global__ void k_init(int N, int B) {
    int i0 = blockIdx.x * blockDim.x + threadIdx.x;
    int stride = gridDim.x * blockDim.x;
    for (int t = i0; t < N; t += stride) { d_deg[t] = 0; d_cursor[t] = 0; }
    for (int t = i0; t < B * 32; t += stride) d_gsum[t] = 0.f;
    for (int t = i0; t < B; t += stride) d_cnt[t] = 0;
}

// ---------------- dense GEMM: Y[N,128] = X[N,128] @ W[128,128] ----------------
// 128x128 block tile, 256 threads, 8x8 register tile per thread, k-tiles of 32.
__global__ void __launch_bounds__(256) k_gemm128(
    const float* __restrict__ X, const float* __restrict__ W,
    float* __restrict__ Y, int nrows)
{
    __shared__ float Xs[128 * 33];   // [row][kk], padded stride 33
    __shared__ float Ws[32 * 129];   // [kk][col], padded stride 129

    int tid = threadIdx.x;
    int tx = tid & 15;         // col group
    int ty = tid >> 4;         // row group
    int rowBase = blockIdx.x * 128;

    float acc[8][8];
#pragma unroll
    for (int i = 0; i < 8; i++)
#pragma unroll
        for (int j = 0; j < 8; j++) acc[i][j] = 0.f;

    for (int k0 = 0; k0 < 128; k0 += 32) {
#pragma unroll
        for (int t = tid; t < 128 * 32; t += 256) {
            int r = t >> 5, kk = t & 31;
            int gr = rowBase + r;
            Xs[r * 33 + kk] = (gr < nrows) ? X[gr * 128 + k0 + kk] : 0.f;
        }
#pragma unroll
        for (int t = tid; t < 32 * 128; t += 256) {
            int kk = t >> 7, c = t & 127;
            Ws[kk * 129 + c] = W[(k0 + kk) * 128 + c];
        }
        __syncthreads();
#pragma unroll
        for (int kk = 0; kk < 32; kk++) {
            float xr[8], wr[8];
#pragma unroll
            for (int i = 0; i < 8; i++) xr[i] = Xs[(ty + 16 * i) * 33 + kk];
#pragma unroll
            for (int j = 0; j < 8; j++) wr[j] = Ws[kk * 129 + tx + 16 * j];
#pragma unroll
            for (int i = 0; i < 8; i++)
#pragma unroll
                for (int j = 0; j < 8; j++)
                    acc[i][j] = fmaf(xr[i], wr[j], acc[i][j]);
        }
        __syncthreads();
    }
#pragma unroll
    for (int i = 0; i < 8; i++) {
        int gr = rowBase + ty + 16 * i;
        if (gr < nrows) {
#pragma unroll
            for (int j = 0; j < 8; j++)
                Y[gr * 128 + tx + 16 * j] = acc[i][j];
        }
    }
}

// ---------------- attention dot products: a[n,h] = <xh[n,h,:], att[h,:]> ----------------
// one warp per node
__global__ void k_attdots(const float* __restrict__ XH,
                          const float* __restrict__ att_s,
                          const float* __restrict__ att_d, int N)
{
    int gw = (blockIdx.x * blockDim.x + threadIdx.x) >> 5;
    int lane = threadIdx.x & 31;
    if (gw >= N) return;
    float s[4], dd[4];
#pragma unroll
    for (int h = 0; h < 4; h++) {
        float v = XH[gw * 128 + h * 32 + lane];
        s[h]  = v * att_s[h * 32 + lane];
        dd[h] = v * att_d[h * 32 + lane];
    }
#pragma unroll
    for (int o = 16; o > 0; o >>= 1) {
#pragma unroll
        for (int h = 0; h < 4; h++) {
            s[h]  += __shfl_xor_sync(0xffffffffu, s[h],  o);
            dd[h] += __shfl_xor_sync(0xffffffffu, dd[h], o);
        }
    }
    if (lane == 0) {
        d_ASRC[gw] = make_float4(s[0], s[1], s[2], s[3]);
        d_ADST[gw] = make_float4(dd[0], dd[1], dd[2], dd[3]);
    }
}

// ---------------- CSR build ----------------
// edge_index is int32 (JAX default x64-disabled downcasts jnp.int64 -> int32)
__global__ void k_deg(const int* __restrict__ ei, int E, int N) {
    int i0 = blockIdx.x * blockDim.x + threadIdx.x;
    int stride = gridDim.x * blockDim.x;
    int T = E + N;
    for (int i = i0; i < T; i += stride) {
        int dd = (i < E) ? ei[E + i] : (i - E);   // self loops appended
        atomicAdd(&d_deg[dd], 1);
    }
}

// single-block warp-shuffle scan: rowptr = exclusive_scan(deg)
__global__ void __launch_bounds__(1024) k_scan(int N) {
    __shared__ int swarp[32];
    __shared__ int s_off;
    int tid = threadIdx.x, lane = tid & 31, wid = tid >> 5;
    if (tid == 0) { s_off = 0; d_rowptr[0] = 0; }
    __syncthreads();
    for (int base = 0; base < N; base += 1024) {
        int i = base + tid;
        int v = (i < N) ? d_deg[i] : 0;
        int x = v;
#pragma unroll
        for (int o = 1; o < 32; o <<= 1) {
            int t = __shfl_up_sync(0xffffffffu, x, o);
            if (lane >= o) x += t;
        }
        if (lane == 31) swarp[wid] = x;
        __syncthreads();
        if (wid == 0) {
            int y = swarp[lane];
#pragma unroll
            for (int o = 1; o < 32; o <<= 1) {
                int t = __shfl_up_sync(0xffffffffu, y, o);
                if (lane >= o) y += t;
            }
            swarp[lane] = y;
        }
        __syncthreads();
        int incl = x + (wid > 0 ? swarp[wid - 1] : 0);
        if (i < N) d_rowptr[i + 1] = s_off + incl;
        int blocktotal = swarp[31];
        __syncthreads();
        if (tid == 0) s_off += blocktotal;
        __syncthreads();
    }
}

__global__ void k_fill(const int* __restrict__ ei, int E, int N) {
    int i0 = blockIdx.x * blockDim.x + threadIdx.x;
    int stride = gridDim.x * blockDim.x;
    int T = E + N;
    for (int i = i0; i < T; i += stride) {
        int s, dd;
        if (i < E) { s = ei[i]; dd = ei[E + i]; }
        else       { s = dd = i - E; }
        int pos = atomicAdd(&d_cursor[dd], 1);
        d_col[d_rowptr[dd] + pos] = s;
    }
}

// ---------------- GAT aggregation with online softmax ----------------
// one block (128 threads) per dst node; thread c owns channel c (head = c/32).
template <bool LAYER2>
__global__ void __launch_bounds__(128) k_agg(
    const float* __restrict__ XH, const float* __restrict__ bias,
    float* __restrict__ OUT, int N)
{
    int n = blockIdx.x;
    int c = threadIdx.x;
    int h = c >> 5;
    int start = d_rowptr[n], end = d_rowptr[n + 1];

    __shared__ int    s_src[32];
    __shared__ float4 s_e4[32];
    __shared__ float  s_red[128];

    float4 ad = d_ADST[n];

    float m = -INFINITY, den = 0.f, acc = 0.f;
    const float* se = (const float*)s_e4;

    for (int k0 = start; k0 < end; k0 += 32) {
        int len = min(32, end - k0);
        if (c < len) {
            int s = d_col[k0 + c];
            s_src[c] = s;
            float4 as = __ldg(&d_ASRC[s]);
            float e0 = as.x + ad.x; e0 = e0 > 0.f ? e0 : 0.2f * e0;
            float e1 = as.y + ad.y; e1 = e1 > 0.f ? e1 : 0.2f * e1;
            float e2 = as.z + ad.z; e2 = e2 > 0.f ? e2 : 0.2f * e2;
            float e3 = as.w + ad.w; e3 = e3 > 0.f ? e3 : 0.2f * e3;
            s_e4[c] = make_float4(e0, e1, e2, e3);
        }
        __syncthreads();

        float cm = m;
        for (int j = 0; j < len; j++) cm = fmaxf(cm, se[j * 4 + h]);
        float scale = __expf(m - cm);   // first chunk: exp(-inf)=0
        acc *= scale; den *= scale;
#pragma unroll 4
        for (int j = 0; j < len; j++) {
            float p = __expf(se[j * 4 + h] - cm);
            den += p;
            acc = fmaf(p, __ldg(&XH[s_src[j] * 128 + c]), acc);
        }
        m = cm;
        __syncthreads();
    }

    float val = acc / (den + 1e-16f);
    if (!LAYER2) {
        val += bias[c];
        OUT[n * 128 + c] = fmaxf(val, 0.f);
    } else {
        s_red[c] = val;
        __syncthreads();
        if (c < 32)
            OUT[n * 32 + c] =
                0.25f * (s_red[c] + s_red[c + 32] + s_red[c + 64] + s_red[c + 96]) + bias[c];
    }
}

// ---------------- global mean pool (sum + count) ----------------
__global__ void k_pool(const float* __restrict__ OUT2,
                       const int* __restrict__ batch, int N)
{
    int i0 = blockIdx.x * blockDim.x + threadIdx.x;
    int stride = gridDim.x * blockDim.x;
    int total = N * 32;
    for (int i = i0; i < total; i += stride) {
        int n = i >> 5, cc = i & 31;
        int b = batch[n];
        atomicAdd(&d_gsum[b * 32 + cc], OUT2[i]);
        if (cc == 0) atomicAdd(&d_cnt[b], 1);
    }
}

// ---------------- final MLP: [B,32+15] -> relu(47->32) -> 32->1 ----------------
__global__ void k_mlp(const float* __restrict__ stats,
                      const float* __restrict__ Wm1, const float* __restrict__ bm1,
                      const float* __restrict__ Wm2, const float* __restrict__ bm2,
                      float* __restrict__ out, int B)
{
    int g = threadIdx.x;
    if (g >= B) return;
    float v[47];
    float inv = 1.f / fmaxf((float)d_cnt[g], 1.f);
#pragma unroll
    for (int cc = 0; cc < 32; cc++) v[cc] = d_gsum[g * 32 + cc] * inv;
#pragma unroll
    for (int f = 0; f < 15; f++) v[32 + f] = stats[g * 15 + f];
    float o = bm2[0];
    for (int k = 0; k < 32; k++) {
        float hsum = bm1[k];
#pragma unroll
        for (int i = 0; i < 47; i++) hsum = fmaf(v[i], Wm1[i * 32 + k], hsum);
        o = fmaf(fmaxf(hsum, 0.f), Wm2[k], o);
    }
    out[g] = o;
}

// ---------------- launch ----------------
extern "C" void kernel_launch(void* const* d_in, const int* in_sizes, int n_in,
                              void* d_out, int out_size)
{
    const float* x     = (const float*)d_in[0];
    const int*   ei    = (const int*)d_in[1];     // int32 (JAX x64 disabled)
    const int*   batch = (const int*)d_in[2];     // int32
    const float* stats = (const float*)d_in[3];
    const float* W1    = (const float*)d_in[4];
    const float* as1   = (const float*)d_in[5];
    const float* ad1   = (const float*)d_in[6];
    const float* b1    = (const float*)d_in[7];
    const float* W2    = (const float*)d_in[8];
    const float* as2   = (const float*)d_in[9];
    const float* ad2   = (const float*)d_in[10];
    const float* b2    = (const float*)d_in[11];
    const float* Wm1   = (const float*)d_in[12];
    const float* bm1   = (const float*)d_in[13];
    const float* Wm2   = (const float*)d_in[14];
    const float* bm2   = (const float*)d_in[15];

    int N = in_sizes[0] / 128;
    int E = in_sizes[1] / 2;
    int B = in_sizes[3] / 15;

    float *XH, *H1, *OUT2;
    cudaGetSymbolAddress((void**)&XH,   d_XH);
    cudaGetSymbolAddress((void**)&H1,   d_H1);
    cudaGetSymbolAddress((void**)&OUT2, d_OUT2);

    int gemmBlocks = (N + 127) / 128;
    int attBlocks  = (N * 32 + 127) / 128;

    k_init<<<256, 256>>>(N, B);

    // CSR build (shared by both layers)
    k_deg <<<512, 256>>>(ei, E, N);
    k_scan<<<1, 1024>>>(N);
    k_fill<<<512, 256>>>(ei, E, N);

    // Layer 1
    k_gemm128<<<gemmBlocks, 256>>>(x, W1, XH, N);
    k_attdots<<<attBlocks, 128>>>(XH, as1, ad1, N);
    k_agg<false><<<N, 128>>>(XH, b1, H1, N);

    // Layer 2
    k_gemm128<<<gemmBlocks, 256>>>(H1, W2, XH, N);
    k_attdots<<<attBlocks, 128>>>(XH, as2, ad2, N);
    k_agg<true><<<N, 128>>>(XH, b2, OUT2, N);

    // Pool + MLP head
    k_pool<<<512, 256>>>(OUT2, batch, N);
    k_mlp<<<1, 128>>>(stats, Wm1, bm1, Wm2, bm2, (float*)d_out, B);
}

// round 4
// speedup vs baseline: 1.6953x; 1.6953x over previous
#include <cuda_runtime.h>
#include <math.h>

#define NMAX 50000
#define EMAX 800000
#define BMAX 128

// ---------------- scratch ----------------
__device__ float  d_XH  [NMAX * 128];
__device__ float  d_H1  [NMAX * 128];
__device__ float  d_OUT2[NMAX * 32];
__device__ float4 d_ASRC[NMAX];
__device__ float4 d_ADST[NMAX];
__device__ int    d_deg   [NMAX];
__device__ int    d_rowptr[NMAX + 1];
__device__ int    d_cursor[NMAX];
__device__ int    d_col   [EMAX + NMAX];
__device__ float  d_gsum  [BMAX * 32];
__device__ int    d_flag  [64];          // chained-scan flags: value = prefix+1, 0 = not ready

// ---------------- init ----------------
__global__ void k_init(int N, int B) {
    int i0 = blockIdx.x * blockDim.x + threadIdx.x;
    int stride = gridDim.x * blockDim.x;
    for (int t = i0; t < N; t += stride) { d_deg[t] = 0; d_cursor[t] = 0; }
    for (int t = i0; t < B * 32; t += stride) d_gsum[t] = 0.f;
    for (int t = i0; t < 64; t += stride) d_flag[t] = (t == 0) ? 1 : 0;
}

// ---------------- GEMM + fused attention dots ----------------
// Y[N,128] = X[N,128] @ W[128,128]; epilogue computes per-row per-head dots
// with att_src/att_dst and writes d_ASRC/d_ADST.
__global__ void __launch_bounds__(256) k_gemm_att(
    const float* __restrict__ X, const float* __restrict__ W,
    const float* __restrict__ att_s, const float* __restrict__ att_d,
    float* __restrict__ Y, int nrows)
{
    __shared__ float Xs[128 * 40];   // [row][kk], stride 40 (float4-aligned, conflict-free)
    __shared__ float Ws[32 * 132];   // [kk][col], stride 132

    int tid = threadIdx.x;
    int tx = tid & 15;
    int ty = tid >> 4;
    int rowBase = blockIdx.x * 128;

    float acc[8][8];
#pragma unroll
    for (int i = 0; i < 8; i++)
#pragma unroll
        for (int j = 0; j < 8; j++) acc[i][j] = 0.f;

    for (int k0 = 0; k0 < 128; k0 += 32) {
#pragma unroll
        for (int it = 0; it < 4; it++) {
            int idx = tid + 256 * it;        // 0..1023 float4s
            int r = idx >> 3;
            int kk4 = (idx & 7) * 4;
            int gr = rowBase + r;
            float4 v = (gr < nrows) ? *(const float4*)&X[gr * 128 + k0 + kk4]
                                    : make_float4(0.f, 0.f, 0.f, 0.f);
            *(float4*)&Xs[r * 40 + kk4] = v;
        }
#pragma unroll
        for (int it = 0; it < 4; it++) {
            int idx = tid + 256 * it;
            int kk = idx >> 5;
            int c4 = (idx & 31) * 4;
            *(float4*)&Ws[kk * 132 + c4] = *(const float4*)&W[(k0 + kk) * 128 + c4];
        }
        __syncthreads();
#pragma unroll
        for (int kk = 0; kk < 32; kk++) {
            float xr[8], wr[8];
#pragma unroll
            for (int i = 0; i < 8; i++) xr[i] = Xs[(ty + 16 * i) * 40 + kk];
#pragma unroll
            for (int j = 0; j < 8; j++) wr[j] = Ws[kk * 132 + tx + 16 * j];
#pragma unroll
            for (int i = 0; i < 8; i++)
#pragma unroll
                for (int j = 0; j < 8; j++)
                    acc[i][j] = fmaf(xr[i], wr[j], acc[i][j]);
        }
        __syncthreads();
    }

    // epilogue: store Y + fused per-head attention dots
    float as_r[8], ad_r[8];
#pragma unroll
    for (int j = 0; j < 8; j++) {
        as_r[j] = att_s[tx + 16 * j];
        ad_r[j] = att_d[tx + 16 * j];
    }
#pragma unroll
    for (int i = 0; i < 8; i++) {
        int gr = rowBase + ty + 16 * i;
        float ps[4], pd[4];
#pragma unroll
        for (int h = 0; h < 4; h++) {
            // cols tx+16*(2h), tx+16*(2h+1) belong to head h
            ps[h] = acc[i][2 * h] * as_r[2 * h] + acc[i][2 * h + 1] * as_r[2 * h + 1];
            pd[h] = acc[i][2 * h] * ad_r[2 * h] + acc[i][2 * h + 1] * ad_r[2 * h + 1];
        }
#pragma unroll
        for (int o = 8; o >= 1; o >>= 1) {
#pragma unroll
            for (int h = 0; h < 4; h++) {
                ps[h] += __shfl_xor_sync(0xffffffffu, ps[h], o);
                pd[h] += __shfl_xor_sync(0xffffffffu, pd[h], o);
            }
        }
        if (gr < nrows) {
#pragma unroll
            for (int j = 0; j < 8; j++)
                Y[gr * 128 + tx + 16 * j] = acc[i][j];
            if (tx == 0) {
                d_ASRC[gr] = make_float4(ps[0], ps[1], ps[2], ps[3]);
                d_ADST[gr] = make_float4(pd[0], pd[1], pd[2], pd[3]);
            }
        }
    }
}

// ---------------- CSR build: 1 thread per edge ----------------
__global__ void k_deg(const int* __restrict__ ei, int E, int N) {
    int i = blockIdx.x * blockDim.x + threadIdx.x;
    int T = E + N;
    if (i >= T) return;
    int dd = (i < E) ? ei[E + i] : (i - E);
    atomicAdd(&d_deg[dd], 1);
}

// chained single-pass scan: block b waits for prefix of block b-1.
// NB = ceil(N/1024) = 49 blocks, all resident simultaneously -> no deadlock.
__global__ void __launch_bounds__(1024) k_scan(int N) {
    __shared__ int swarp[32];
    __shared__ int s_prev;
    int b = blockIdx.x;
    int tid = threadIdx.x, lane = tid & 31, wid = tid >> 5;
    int i = b * 1024 + tid;
    int v = (i < N) ? d_deg[i] : 0;
    int x = v;
#pragma unroll
    for (int o = 1; o < 32; o <<= 1) {
        int t = __shfl_up_sync(0xffffffffu, x, o);
        if (lane >= o) x += t;
    }
    if (lane == 31) swarp[wid] = x;
    __syncthreads();
    if (wid == 0) {
        int y = swarp[lane];
#pragma unroll
        for (int o = 1; o < 32; o <<= 1) {
            int t = __shfl_up_sync(0xffffffffu, y, o);
            if (lane >= o) y += t;
        }
        swarp[lane] = y;
    }
    __syncthreads();
    int incl = x + (wid > 0 ? swarp[wid - 1] : 0);
    int total = swarp[31];
    if (tid == 0) {
        int fv;
        while ((fv = ((volatile int*)d_flag)[b]) == 0) { }
        int prev = fv - 1;
        ((volatile int*)d_flag)[b + 1] = prev + total + 1;
        s_prev = prev;
        if (b == 0) d_rowptr[0] = 0;
    }
    __syncthreads();
    if (i < N) d_rowptr[i + 1] = s_prev + incl;
}

__global__ void k_fill(const int* __restrict__ ei, int E, int N) {
    int i = blockIdx.x * blockDim.x + threadIdx.x;
    int T = E + N;
    if (i >= T) return;
    int s, dd;
    if (i < E) { s = ei[i]; dd = ei[E + i]; }
    else       { s = dd = i - E; }
    int pos = atomicAdd(&d_cursor[dd], 1);
    d_col[d_rowptr[dd] + pos] = s;
}

// ---------------- GAT aggregation: warp per node, lane owns 4 channels ----------------
template <bool LAYER2>
__global__ void __launch_bounds__(128) k_agg(
    const float4* __restrict__ XH4, const float* __restrict__ bias,
    float* __restrict__ OUT, int N)
{
    __shared__ float4 s_e4[4][32];
    __shared__ int    s_src[4][32];

    int tid = threadIdx.x;
    int w = tid >> 5, lane = tid & 31;
    int n = blockIdx.x * 4 + w;
    if (n >= N) return;
    int h = lane >> 3;                 // head of my 4 channels

    int start = d_rowptr[n], end = d_rowptr[n + 1];
    float4 ad = d_ADST[n];

    float m = -INFINITY, den = 0.f;
    float4 acc = make_float4(0.f, 0.f, 0.f, 0.f);
    const float* se = (const float*)&s_e4[w][0];
    const int*   ss = &s_src[w][0];

    for (int k0 = start; k0 < end; k0 += 32) {
        int len = min(32, end - k0);
        float4 e4 = make_float4(-INFINITY, -INFINITY, -INFINITY, -INFINITY);
        int s = 0;
        if (lane < len) {
            s = __ldg(&d_col[k0 + lane]);
            float4 as = __ldg(&d_ASRC[s]);
            e4.x = as.x + ad.x; e4.x = e4.x > 0.f ? e4.x : 0.2f * e4.x;
            e4.y = as.y + ad.y; e4.y = e4.y > 0.f ? e4.y : 0.2f * e4.y;
            e4.z = as.z + ad.z; e4.z = e4.z > 0.f ? e4.z : 0.2f * e4.z;
            e4.w = as.w + ad.w; e4.w = e4.w > 0.f ? e4.w : 0.2f * e4.w;
        }
        s_src[w][lane] = s;
        s_e4[w][lane] = e4;

        // chunk max per head via warp shfl (lanes >= len hold -inf)
        float4 mx = e4;
#pragma unroll
        for (int o = 16; o >= 1; o >>= 1) {
            mx.x = fmaxf(mx.x, __shfl_xor_sync(0xffffffffu, mx.x, o));
            mx.y = fmaxf(mx.y, __shfl_xor_sync(0xffffffffu, mx.y, o));
            mx.z = fmaxf(mx.z, __shfl_xor_sync(0xffffffffu, mx.z, o));
            mx.w = fmaxf(mx.w, __shfl_xor_sync(0xffffffffu, mx.w, o));
        }
        float cmh = (h == 0) ? mx.x : (h == 1) ? mx.y : (h == 2) ? mx.z : mx.w;
        float cm = fmaxf(m, cmh);
        float scale = __expf(m - cm);      // first chunk: exp(-inf) = 0
        acc.x *= scale; acc.y *= scale; acc.z *= scale; acc.w *= scale;
        den *= scale;

        __syncwarp();
#pragma unroll 4
        for (int j = 0; j < len; j++) {
            float p = __expf(se[j * 4 + h] - cm);
            den += p;
            float4 xv = __ldg(&XH4[ss[j] * 32 + lane]);
            acc.x = fmaf(p, xv.x, acc.x);
            acc.y = fmaf(p, xv.y, acc.y);
            acc.z = fmaf(p, xv.z, acc.z);
            acc.w = fmaf(p, xv.w, acc.w);
        }
        m = cm;
        __syncwarp();
    }

    float inv = 1.f / (den + 1e-16f);
    float4 val = make_float4(acc.x * inv, acc.y * inv, acc.z * inv, acc.w * inv);

    if (!LAYER2) {
        float4 b4 = ((const float4*)bias)[lane];
        val.x = fmaxf(val.x + b4.x, 0.f);
        val.y = fmaxf(val.y + b4.y, 0.f);
        val.z = fmaxf(val.z + b4.z, 0.f);
        val.w = fmaxf(val.w + b4.w, 0.f);
        ((float4*)OUT)[n * 32 + lane] = val;
    } else {
        // mean over 4 heads: lanes {l, l^8, l^16, l^24} hold same in-head channels
#pragma unroll
        for (int o = 8; o <= 16; o <<= 1) {
            val.x += __shfl_xor_sync(0xffffffffu, val.x, o);
            val.y += __shfl_xor_sync(0xffffffffu, val.y, o);
            val.z += __shfl_xor_sync(0xffffffffu, val.z, o);
            val.w += __shfl_xor_sync(0xffffffffu, val.w, o);
        }
        if (lane < 8) {
            float4 b4 = ((const float4*)bias)[lane];
            float4 o4 = make_float4(0.25f * val.x + b4.x, 0.25f * val.y + b4.y,
                                    0.25f * val.z + b4.z, 0.25f * val.w + b4.w);
            ((float4*)OUT)[n * 8 + lane] = o4;
        }
    }
}

// ---------------- global mean pool: batch is sorted -> register runs ----------------
__global__ void k_pool(const float* __restrict__ OUT2,
                       const int* __restrict__ batch, int N)
{
    int perBlock = (N + gridDim.x - 1) / gridDim.x;
    int n0 = blockIdx.x * perBlock;
    int n1 = min(N, n0 + perBlock);
    int ch  = threadIdx.x & 31;
    int sub = threadIdx.x >> 5;      // 0..7
    float sum = 0.f;
    int curb = -1;
    for (int n = n0 + sub; n < n1; n += 8) {
        int b = batch[n];
        if (b != curb) {
            if (curb >= 0) atomicAdd(&d_gsum[curb * 32 + ch], sum);
            curb = b; sum = 0.f;
        }
        sum += OUT2[n * 32 + ch];
    }
    if (curb >= 0) atomicAdd(&d_gsum[curb * 32 + ch], sum);
}

// ---------------- final MLP; counts via binary search on sorted batch ----------------
__global__ void k_mlp(const int* __restrict__ batch, int N,
                      const float* __restrict__ stats,
                      const float* __restrict__ Wm1, const float* __restrict__ bm1,
                      const float* __restrict__ Wm2, const float* __restrict__ bm2,
                      float* __restrict__ out, int B)
{
    int g = threadIdx.x;
    if (g >= B) return;
    // lower_bound(g) and lower_bound(g+1)
    int lo0 = 0, hi0 = N;
    while (lo0 < hi0) { int mid = (lo0 + hi0) >> 1; if (batch[mid] < g) lo0 = mid + 1; else hi0 = mid; }
    int lo1 = lo0, hi1 = N;
    while (lo1 < hi1) { int mid = (lo1 + hi1) >> 1; if (batch[mid] < g + 1) lo1 = mid + 1; else hi1 = mid; }
    float cnt = (float)(lo1 - lo0);
    float inv = 1.f / fmaxf(cnt, 1.f);

    float v[47];
#pragma unroll
    for (int cc = 0; cc < 32; cc++) v[cc] = d_gsum[g * 32 + cc] * inv;
#pragma unroll
    for (int f = 0; f < 15; f++) v[32 + f] = stats[g * 15 + f];
    float o = bm2[0];
    for (int k = 0; k < 32; k++) {
        float hsum = bm1[k];
#pragma unroll
        for (int i = 0; i < 47; i++) hsum = fmaf(v[i], Wm1[i * 32 + k], hsum);
        o = fmaf(fmaxf(hsum, 0.f), Wm2[k], o);
    }
    out[g] = o;
}

// ---------------- launch ----------------
extern "C" void kernel_launch(void* const* d_in, const int* in_sizes, int n_in,
                              void* d_out, int out_size)
{
    const float* x     = (const float*)d_in[0];
    const int*   ei    = (const int*)d_in[1];
    const int*   batch = (const int*)d_in[2];
    const float* stats = (const float*)d_in[3];
    const float* W1    = (const float*)d_in[4];
    const float* as1   = (const float*)d_in[5];
    const float* ad1   = (const float*)d_in[6];
    const float* b1    = (const float*)d_in[7];
    const float* W2    = (const float*)d_in[8];
    const float* as2   = (const float*)d_in[9];
    const float* ad2   = (const float*)d_in[10];
    const float* b2    = (const float*)d_in[11];
    const float* Wm1   = (const float*)d_in[12];
    const float* bm1   = (const float*)d_in[13];
    const float* Wm2   = (const float*)d_in[14];
    const float* bm2   = (const float*)d_in[15];

    int N = in_sizes[0] / 128;
    int E = in_sizes[1] / 2;
    int B = in_sizes[3] / 15;

    float *XH, *H1, *OUT2;
    cudaGetSymbolAddress((void**)&XH,   d_XH);
    cudaGetSymbolAddress((void**)&H1,   d_H1);
    cudaGetSymbolAddress((void**)&OUT2, d_OUT2);

    int gemmBlocks = (N + 127) / 128;
    int edgeBlocks = (E + N + 255) / 256;
    int aggBlocks  = (N + 3) / 4;
    int scanBlocks = (N + 1023) / 1024;

    k_init<<<64, 256>>>(N, B);

    k_deg <<<edgeBlocks, 256>>>(ei, E, N);
    k_scan<<<scanBlocks, 1024>>>(N);
    k_fill<<<edgeBlocks, 256>>>(ei, E, N);

    k_gemm_att<<<gemmBlocks, 256>>>(x, W1, as1, ad1, XH, N);
    k_agg<false><<<aggBlocks, 128>>>((const float4*)XH, b1, H1, N);

    k_gemm_att<<<gemmBlocks, 256>>>(H1, W2, as2, ad2, XH, N);
    k_agg<true><<<aggBlocks, 128>>>((const float4*)XH, b2, OUT2, N);

    k_pool<<<128, 256>>>(OUT2, batch, N);
    k_mlp<<<1, 128>>>(batch, N, stats, Wm1, bm1, Wm2, bm2, (float*)d_out, B);
}

// round 5
// speedup vs baseline: 1.7941x; 1.0583x over previous
#include <cuda_runtime.h>
#include <cuda_fp16.h>
#include <math.h>

#define NMAX 50000
#define EMAX 800000
#define BMAX 128

// ---------------- scratch ----------------
__device__ __half2 d_XHh [NMAX * 64];    // GEMM output in fp16 (128 ch = 64 half2 per node)
__device__ float   d_H1  [NMAX * 128];   // layer-1 output (fp32, GEMM2 input)
__device__ float   d_OUT2[NMAX * 32];
__device__ float4  d_ASRC[NMAX];
__device__ float4  d_ADST[NMAX];
__device__ int     d_deg   [NMAX];
__device__ int     d_rowptr[NMAX + 1];
__device__ int     d_cursor[NMAX];
__device__ int     d_col   [EMAX + NMAX];
__device__ float   d_gsum  [BMAX * 32];
__device__ int     d_flag  [64];         // chained-scan flags: value = prefix+1, 0 = not ready

// ---------------- init ----------------
__global__ void k_init(int N, int B) {
    int i0 = blockIdx.x * blockDim.x + threadIdx.x;
    int stride = gridDim.x * blockDim.x;
    for (int t = i0; t < N; t += stride) { d_deg[t] = 0; d_cursor[t] = 0; }
    for (int t = i0; t < B * 32; t += stride) d_gsum[t] = 0.f;
    for (int t = i0; t < 64; t += stride) d_flag[t] = (t == 0) ? 1 : 0;
}

// ---------------- GEMM + fused attention dots, fp16 output ----------------
// XHh[N,128](fp16) = X[N,128] @ W[128,128]; epilogue computes per-head dots
// against att_src/att_dst (fp32-exact) and writes d_ASRC/d_ADST.
__global__ void __launch_bounds__(256) k_gemm_att(
    const float* __restrict__ X, const float* __restrict__ W,
    const float* __restrict__ att_s, const float* __restrict__ att_d,
    int nrows)
{
    __shared__ float Xs[128 * 40];   // [row][kk], float4-aligned, conflict-free
    __shared__ float Ws[32 * 132];   // [kk][col]

    int tid = threadIdx.x;
    int tx = tid & 15;
    int ty = tid >> 4;
    int rowBase = blockIdx.x * 128;

    float acc[8][8];
#pragma unroll
    for (int i = 0; i < 8; i++)
#pragma unroll
        for (int j = 0; j < 8; j++) acc[i][j] = 0.f;

    for (int k0 = 0; k0 < 128; k0 += 32) {
#pragma unroll
        for (int it = 0; it < 4; it++) {
            int idx = tid + 256 * it;
            int r = idx >> 3;
            int kk4 = (idx & 7) * 4;
            int gr = rowBase + r;
            float4 v = (gr < nrows) ? *(const float4*)&X[gr * 128 + k0 + kk4]
                                    : make_float4(0.f, 0.f, 0.f, 0.f);
            *(float4*)&Xs[r * 40 + kk4] = v;
        }
#pragma unroll
        for (int it = 0; it < 4; it++) {
            int idx = tid + 256 * it;
            int kk = idx >> 5;
            int c4 = (idx & 31) * 4;
            *(float4*)&Ws[kk * 132 + c4] = *(const float4*)&W[(k0 + kk) * 128 + c4];
        }
        __syncthreads();
#pragma unroll
        for (int kk = 0; kk < 32; kk++) {
            float xr[8], wr[8];
#pragma unroll
            for (int i = 0; i < 8; i++) xr[i] = Xs[(ty + 16 * i) * 40 + kk];
#pragma unroll
            for (int j = 0; j < 8; j++) wr[j] = Ws[kk * 132 + tx + 16 * j];
#pragma unroll
            for (int i = 0; i < 8; i++)
#pragma unroll
                for (int j = 0; j < 8; j++)
                    acc[i][j] = fmaf(xr[i], wr[j], acc[i][j]);
        }
        __syncthreads();
    }

    // epilogue: fp16 store + fused per-head attention dots
    float as_r[8], ad_r[8];
#pragma unroll
    for (int j = 0; j < 8; j++) {
        as_r[j] = att_s[tx + 16 * j];
        ad_r[j] = att_d[tx + 16 * j];
    }
    bool lowlane = ((tx & 1) == 0);
#pragma unroll
    for (int i = 0; i < 8; i++) {
        int gr = rowBase + ty + 16 * i;
        float ps[4], pd[4];
#pragma unroll
        for (int h = 0; h < 4; h++) {
            ps[h] = acc[i][2 * h] * as_r[2 * h] + acc[i][2 * h + 1] * as_r[2 * h + 1];
            pd[h] = acc[i][2 * h] * ad_r[2 * h] + acc[i][2 * h + 1] * ad_r[2 * h + 1];
        }
#pragma unroll
        for (int o = 8; o >= 1; o >>= 1) {
#pragma unroll
            for (int h = 0; h < 4; h++) {
                ps[h] += __shfl_xor_sync(0xffffffffu, ps[h], o);
                pd[h] += __shfl_xor_sync(0xffffffffu, pd[h], o);
            }
        }
        // half2 packing: even-tx lane pairs (col c, c+1); shfl outside predication
#pragma unroll
        for (int j = 0; j < 8; j++) {
            float nb = __shfl_xor_sync(0xffffffffu, acc[i][j], 1);
            if (lowlane && gr < nrows) {
                __half2 h2 = __floats2half2_rn(acc[i][j], nb);
                d_XHh[gr * 64 + (tx >> 1) + 8 * j] = h2;   // half2 idx = col/2
            }
        }
        if (gr < nrows && tx == 0) {
            d_ASRC[gr] = make_float4(ps[0], ps[1], ps[2], ps[3]);
            d_ADST[gr] = make_float4(pd[0], pd[1], pd[2], pd[3]);
        }
    }
}

// ---------------- CSR build: 1 thread per edge ----------------
__global__ void k_deg(const int* __restrict__ ei, int E, int N) {
    int i = blockIdx.x * blockDim.x + threadIdx.x;
    int T = E + N;
    if (i >= T) return;
    int dd = (i < E) ? ei[E + i] : (i - E);
    atomicAdd(&d_deg[dd], 1);
}

// chained single-pass scan (49 blocks, dispatch in bid order -> progress guaranteed)
__global__ void __launch_bounds__(1024) k_scan(int N) {
    __shared__ int swarp[32];
    __shared__ int s_prev;
    int b = blockIdx.x;
    int tid = threadIdx.x, lane = tid & 31, wid = tid >> 5;
    int i = b * 1024 + tid;
    int v = (i < N) ? d_deg[i] : 0;
    int x = v;
#pragma unroll
    for (int o = 1; o < 32; o <<= 1) {
        int t = __shfl_up_sync(0xffffffffu, x, o);
        if (lane >= o) x += t;
    }
    if (lane == 31) swarp[wid] = x;
    __syncthreads();
    if (wid == 0) {
        int y = swarp[lane];
#pragma unroll
        for (int o = 1; o < 32; o <<= 1) {
            int t = __shfl_up_sync(0xffffffffu, y, o);
            if (lane >= o) y += t;
        }
        swarp[lane] = y;
    }
    __syncthreads();
    int incl = x + (wid > 0 ? swarp[wid - 1] : 0);
    int total = swarp[31];
    if (tid == 0) {
        int fv;
        while ((fv = ((volatile int*)d_flag)[b]) == 0) { }
        int prev = fv - 1;
        ((volatile int*)d_flag)[b + 1] = prev + total + 1;
        s_prev = prev;
        if (b == 0) d_rowptr[0] = 0;
    }
    __syncthreads();
    if (i < N) d_rowptr[i + 1] = s_prev + incl;
}

__global__ void k_fill(const int* __restrict__ ei, int E, int N) {
    int i = blockIdx.x * blockDim.x + threadIdx.x;
    int T = E + N;
    if (i >= T) return;
    int s, dd;
    if (i < E) { s = ei[i]; dd = ei[E + i]; }
    else       { s = dd = i - E; }
    int pos = atomicAdd(&d_cursor[dd], 1);
    d_col[d_rowptr[dd] + pos] = s;
}

// ---------------- GAT aggregation: warp per node, lane owns 4 channels (fp16 gather) ----------------
template <bool LAYER2>
__global__ void __launch_bounds__(128) k_agg(
    const float* __restrict__ bias, float* __restrict__ OUT, int N)
{
    __shared__ float4 s_e4[4][32];
    __shared__ int    s_src[4][32];

    int tid = threadIdx.x;
    int w = tid >> 5, lane = tid & 31;
    int n = blockIdx.x * 4 + w;
    if (n >= N) return;
    int h = lane >> 3;

    int start = d_rowptr[n], end = d_rowptr[n + 1];
    float4 ad = d_ADST[n];

    float m = -INFINITY, den = 0.f;
    float4 acc = make_float4(0.f, 0.f, 0.f, 0.f);
    const float* se = (const float*)&s_e4[w][0];
    const int*   ss = &s_src[w][0];
    const uint2* XH8 = (const uint2*)d_XHh;   // 8B per lane = channels 4l..4l+3

    for (int k0 = start; k0 < end; k0 += 32) {
        int len = min(32, end - k0);
        float4 e4 = make_float4(-INFINITY, -INFINITY, -INFINITY, -INFINITY);
        int s = 0;
        if (lane < len) {
            s = __ldg(&d_col[k0 + lane]);
            float4 as = __ldg(&d_ASRC[s]);
            e4.x = as.x + ad.x; e4.x = e4.x > 0.f ? e4.x : 0.2f * e4.x;
            e4.y = as.y + ad.y; e4.y = e4.y > 0.f ? e4.y : 0.2f * e4.y;
            e4.z = as.z + ad.z; e4.z = e4.z > 0.f ? e4.z : 0.2f * e4.z;
            e4.w = as.w + ad.w; e4.w = e4.w > 0.f ? e4.w : 0.2f * e4.w;
        }
        s_src[w][lane] = s;
        s_e4[w][lane] = e4;

        float4 mx = e4;
#pragma unroll
        for (int o = 16; o >= 1; o >>= 1) {
            mx.x = fmaxf(mx.x, __shfl_xor_sync(0xffffffffu, mx.x, o));
            mx.y = fmaxf(mx.y, __shfl_xor_sync(0xffffffffu, mx.y, o));
            mx.z = fmaxf(mx.z, __shfl_xor_sync(0xffffffffu, mx.z, o));
            mx.w = fmaxf(mx.w, __shfl_xor_sync(0xffffffffu, mx.w, o));
        }
        float cmh = (h == 0) ? mx.x : (h == 1) ? mx.y : (h == 2) ? mx.z : mx.w;
        float cm = fmaxf(m, cmh);
        float scale = __expf(m - cm);
        acc.x *= scale; acc.y *= scale; acc.z *= scale; acc.w *= scale;
        den *= scale;

        __syncwarp();
#pragma unroll 4
        for (int j = 0; j < len; j++) {
            float p = __expf(se[j * 4 + h] - cm);
            den += p;
            uint2 r = __ldg(&XH8[ss[j] * 32 + lane]);
            float2 f0 = __half22float2(*(const __half2*)&r.x);
            float2 f1 = __half22float2(*(const __half2*)&r.y);
            acc.x = fmaf(p, f0.x, acc.x);
            acc.y = fmaf(p, f0.y, acc.y);
            acc.z = fmaf(p, f1.x, acc.z);
            acc.w = fmaf(p, f1.y, acc.w);
        }
        m = cm;
        __syncwarp();
    }

    float inv = 1.f / (den + 1e-16f);
    float4 val = make_float4(acc.x * inv, acc.y * inv, acc.z * inv, acc.w * inv);

    if (!LAYER2) {
        float4 b4 = ((const float4*)bias)[lane];
        val.x = fmaxf(val.x + b4.x, 0.f);
        val.y = fmaxf(val.y + b4.y, 0.f);
        val.z = fmaxf(val.z + b4.z, 0.f);
        val.w = fmaxf(val.w + b4.w, 0.f);
        ((float4*)OUT)[n * 32 + lane] = val;
    } else {
#pragma unroll
        for (int o = 8; o <= 16; o <<= 1) {
            val.x += __shfl_xor_sync(0xffffffffu, val.x, o);
            val.y += __shfl_xor_sync(0xffffffffu, val.y, o);
            val.z += __shfl_xor_sync(0xffffffffu, val.z, o);
            val.w += __shfl_xor_sync(0xffffffffu, val.w, o);
        }
        if (lane < 8) {
            float4 b4 = ((const float4*)bias)[lane];
            float4 o4 = make_float4(0.25f * val.x + b4.x, 0.25f * val.y + b4.y,
                                    0.25f * val.z + b4.z, 0.25f * val.w + b4.w);
            ((float4*)OUT)[n * 8 + lane] = o4;
        }
    }
}

// ---------------- global mean pool: batch sorted -> register runs ----------------
__global__ void k_pool(const float* __restrict__ OUT2,
                       const int* __restrict__ batch, int N)
{
    int perBlock = (N + gridDim.x - 1) / gridDim.x;
    int n0 = blockIdx.x * perBlock;
    int n1 = min(N, n0 + perBlock);
    int ch  = threadIdx.x & 31;
    int sub = threadIdx.x >> 5;
    float sum = 0.f;
    int curb = -1;
    for (int n = n0 + sub; n < n1; n += 8) {
        int b = batch[n];
        if (b != curb) {
            if (curb >= 0) atomicAdd(&d_gsum[curb * 32 + ch], sum);
            curb = b; sum = 0.f;
        }
        sum += OUT2[n * 32 + ch];
    }
    if (curb >= 0) atomicAdd(&d_gsum[curb * 32 + ch], sum);
}

// ---------------- final MLP; counts via binary search on sorted batch ----------------
__global__ void k_mlp(const int* __restrict__ batch, int N,
                      const float* __restrict__ stats,
                      const float* __restrict__ Wm1, const float* __restrict__ bm1,
                      const float* __restrict__ Wm2, const float* __restrict__ bm2,
                      float* __restrict__ out, int B)
{
    int g = threadIdx.x;
    if (g >= B) return;
    int lo0 = 0, hi0 = N;
    while (lo0 < hi0) { int mid = (lo0 + hi0) >> 1; if (batch[mid] < g) lo0 = mid + 1; else hi0 = mid; }
    int lo1 = lo0, hi1 = N;
    while (lo1 < hi1) { int mid = (lo1 + hi1) >> 1; if (batch[mid] < g + 1) lo1 = mid + 1; else hi1 = mid; }
    float cnt = (float)(lo1 - lo0);
    float inv = 1.f / fmaxf(cnt, 1.f);

    float v[47];
#pragma unroll
    for (int cc = 0; cc < 32; cc++) v[cc] = d_gsum[g * 32 + cc] * inv;
#pragma unroll
    for (int f = 0; f < 15; f++) v[32 + f] = stats[g * 15 + f];
    float o = bm2[0];
    for (int k = 0; k < 32; k++) {
        float hsum = bm1[k];
#pragma unroll
        for (int i = 0; i < 47; i++) hsum = fmaf(v[i], Wm1[i * 32 + k], hsum);
        o = fmaf(fmaxf(hsum, 0.f), Wm2[k], o);
    }
    out[g] = o;
}

// ---------------- launch ----------------
extern "C" void kernel_launch(void* const* d_in, const int* in_sizes, int n_in,
                              void* d_out, int out_size)
{
    const float* x     = (const float*)d_in[0];
    const int*   ei    = (const int*)d_in[1];
    const int*   batch = (const int*)d_in[2];
    const float* stats = (const float*)d_in[3];
    const float* W1    = (const float*)d_in[4];
    const float* as1   = (const float*)d_in[5];
    const float* ad1   = (const float*)d_in[6];
    const float* b1    = (const float*)d_in[7];
    const float* W2    = (const float*)d_in[8];
    const float* as2   = (const float*)d_in[9];
    const float* ad2   = (const float*)d_in[10];
    const float* b2    = (const float*)d_in[11];
    const float* Wm1   = (const float*)d_in[12];
    const float* bm1   = (const float*)d_in[13];
    const float* Wm2   = (const float*)d_in[14];
    const float* bm2   = (const float*)d_in[15];

    int N = in_sizes[0] / 128;
    int E = in_sizes[1] / 2;
    int B = in_sizes[3] / 15;

    float *H1, *OUT2;
    cudaGetSymbolAddress((void**)&H1,   d_H1);
    cudaGetSymbolAddress((void**)&OUT2, d_OUT2);

    // side stream + events for CSR || GEMM1 overlap (created once; host objects only)
    static cudaStream_t s_side = nullptr;
    static cudaEvent_t  s_ev0 = nullptr, s_ev1 = nullptr;
    if (!s_side) {
        cudaStreamCreateWithFlags(&s_side, cudaStreamNonBlocking);
        cudaEventCreateWithFlags(&s_ev0, cudaEventDisableTiming);
        cudaEventCreateWithFlags(&s_ev1, cudaEventDisableTiming);
    }

    int gemmBlocks = (N + 127) / 128;
    int edgeBlocks = (E + N + 255) / 256;
    int aggBlocks  = (N + 3) / 4;
    int scanBlocks = (N + 1023) / 1024;

    k_init<<<64, 256>>>(N, B);
    cudaEventRecord(s_ev0, 0);
    cudaStreamWaitEvent(s_side, s_ev0, 0);

    // CSR build on side stream, overlapped with GEMM1
    k_deg <<<edgeBlocks, 256, 0, s_side>>>(ei, E, N);
    k_scan<<<scanBlocks, 1024, 0, s_side>>>(N);
    k_fill<<<edgeBlocks, 256, 0, s_side>>>(ei, E, N);
    cudaEventRecord(s_ev1, s_side);

    k_gemm_att<<<gemmBlocks, 256>>>(x, W1, as1, ad1, N);

    cudaStreamWaitEvent(0, s_ev1, 0);   // join: agg needs CSR + GEMM1
    k_agg<false><<<aggBlocks, 128>>>(b1, H1, N);

    k_gemm_att<<<gemmBlocks, 256>>>(H1, W2, as2, ad2, N);
    k_agg<true><<<aggBlocks, 128>>>(b2, OUT2, N);

    k_pool<<<128, 256>>>(OUT2, batch, N);
    k_mlp<<<1, 128>>>(batch, N, stats, Wm1, bm1, Wm2, bm2, (float*)d_out, B);
}

// round 7
// speedup vs baseline: 2.1697x; 1.2093x over previous
#include <cuda_runtime.h>
#include <cuda_fp16.h>
#include <stdint.h>
#include <math.h>

#define NMAX 50000
#define EMAX 800000
#define BMAX 128

// ---------------- scratch ----------------
__device__ __half2 d_XHh [NMAX * 64];    // GEMM output fp16 (128 ch = 64 half2/node)
__device__ float   d_H1  [NMAX * 128];   // layer-1 output (fp32, GEMM2 input)
__device__ float   d_OUT2[NMAX * 32];
__device__ float4  d_ASRC[NMAX];
__device__ float4  d_ADST[NMAX];
__device__ int     d_deg   [NMAX];
__device__ int     d_rowptr[NMAX + 1];
__device__ int     d_cursor[NMAX];
__device__ int     d_col   [EMAX + NMAX];
__device__ float   d_gsum  [BMAX * 32];
__device__ int     d_flag  [64];

// ---------------- init ----------------
__global__ void k_init(int N, int B) {
    int i0 = blockIdx.x * blockDim.x + threadIdx.x;
    int stride = gridDim.x * blockDim.x;
    for (int t = i0; t < N; t += stride) { d_deg[t] = 0; d_cursor[t] = 0; }
    for (int t = i0; t < B * 32; t += stride) d_gsum[t] = 0.f;
    for (int t = i0; t < 64; t += stride) d_flag[t] = (t == 0) ? 1 : 0;
}

// ---------------- tensor-core GEMM + fused attention dots, fp16 output ----------------
// XHh[N,128] = fp16(X[N,128] @ W[128,128]); dots vs att_src/att_dst -> d_ASRC/d_ADST.
// mma.sync.m16n8k16 f16xf16+f32. CTA tile 128x128, 8 warps (4 row-groups x 2 col-groups),
// warp tile 32x64. Xs padded to 72 halves/row -> conflict-free direct fragment loads.
__global__ void __launch_bounds__(256) k_gemm_att(
    const float* __restrict__ X, const float* __restrict__ W,
    const float* __restrict__ att_s, const float* __restrict__ att_d,
    int nrows)
{
    __shared__ __half Xs[128][72];
    __shared__ __half Wt[128][72];    // transposed: Wt[n][k]
    __shared__ float  s_ps[128][4];
    __shared__ float  s_pd[128][4];

    int tid = threadIdx.x;
    int wid = tid >> 5, lane = tid & 31;
    int g = lane >> 2, t = lane & 3;
    int wr = wid >> 1, wc = wid & 1;
    int rowBase = blockIdx.x * 128;

    float acc[2][8][4];
#pragma unroll
    for (int mi = 0; mi < 2; mi++)
#pragma unroll
        for (int ni = 0; ni < 8; ni++)
#pragma unroll
            for (int q = 0; q < 4; q++) acc[mi][ni][q] = 0.f;

    for (int k0 = 0; k0 < 128; k0 += 64) {
        // Xs: 128 rows x 64 k, fp32 -> fp16 inline
#pragma unroll
        for (int it = 0; it < 8; it++) {
            int idx = tid + 256 * it;          // 2048 float4s
            int r = idx >> 4;
            int c4 = (idx & 15) * 4;
            int gr = rowBase + r;
            float4 v = (gr < nrows) ? *(const float4*)&X[gr * 128 + k0 + c4]
                                    : make_float4(0.f, 0.f, 0.f, 0.f);
            *(__half2*)&Xs[r][c4]     = __floats2half2_rn(v.x, v.y);
            *(__half2*)&Xs[r][c4 + 2] = __floats2half2_rn(v.z, v.w);
        }
        // Wt: transpose W[k][n] -> Wt[n][k], fp32 -> fp16
#pragma unroll
        for (int it = 0; it < 8; it++) {
            int idx = tid + 256 * it;          // 64 k x 32 n4
            int k = idx >> 5;
            int n4 = (idx & 31) * 4;
            float4 v = *(const float4*)&W[(k0 + k) * 128 + n4];
            Wt[n4][k]     = __float2half_rn(v.x);
            Wt[n4 + 1][k] = __float2half_rn(v.y);
            Wt[n4 + 2][k] = __float2half_rn(v.z);
            Wt[n4 + 3][k] = __float2half_rn(v.w);
        }
        __syncthreads();
#pragma unroll
        for (int ks = 0; ks < 4; ks++) {
            int kb = ks * 16;
            uint32_t a[2][4];
#pragma unroll
            for (int mi = 0; mi < 2; mi++) {
                int ar = wr * 32 + mi * 16 + g;
                a[mi][0] = *(const uint32_t*)&Xs[ar][kb + 2 * t];
                a[mi][1] = *(const uint32_t*)&Xs[ar + 8][kb + 2 * t];
                a[mi][2] = *(const uint32_t*)&Xs[ar][kb + 2 * t + 8];
                a[mi][3] = *(const uint32_t*)&Xs[ar + 8][kb + 2 * t + 8];
            }
#pragma unroll
            for (int ni = 0; ni < 8; ni++) {
                int bn = wc * 64 + ni * 8 + g;
                uint32_t b0 = *(const uint32_t*)&Wt[bn][kb + 2 * t];
                uint32_t b1 = *(const uint32_t*)&Wt[bn][kb + 2 * t + 8];
#pragma unroll
                for (int mi = 0; mi < 2; mi++) {
                    asm volatile(
                        "mma.sync.aligned.m16n8k16.row.col.f32.f16.f16.f32 "
                        "{%0,%1,%2,%3}, {%4,%5,%6,%7}, {%8,%9}, {%0,%1,%2,%3};"
                        : "+f"(acc[mi][ni][0]), "+f"(acc[mi][ni][1]),
                          "+f"(acc[mi][ni][2]), "+f"(acc[mi][ni][3])
                        : "r"(a[mi][0]), "r"(a[mi][1]), "r"(a[mi][2]), "r"(a[mi][3]),
                          "r"(b0), "r"(b1));
                }
            }
        }
        __syncthreads();
    }

    // ---- epilogue: attention dots (no atomics; (row,head) has unique owner) ----
#pragma unroll
    for (int mi = 0; mi < 2; mi++) {
        float ps[2][2] = {{0.f, 0.f}, {0.f, 0.f}};
        float pd[2][2] = {{0.f, 0.f}, {0.f, 0.f}};
#pragma unroll
        for (int ni = 0; ni < 8; ni++) {
            int col = wc * 64 + ni * 8 + 2 * t;
            float s0 = att_s[col], s1 = att_s[col + 1];
            float dd0 = att_d[col], dd1 = att_d[col + 1];
            int hl = ni >> 2;
            ps[0][hl] += acc[mi][ni][0] * s0 + acc[mi][ni][1] * s1;
            ps[1][hl] += acc[mi][ni][2] * s0 + acc[mi][ni][3] * s1;
            pd[0][hl] += acc[mi][ni][0] * dd0 + acc[mi][ni][1] * dd1;
            pd[1][hl] += acc[mi][ni][2] * dd0 + acc[mi][ni][3] * dd1;
        }
#pragma unroll
        for (int o = 1; o <= 2; o <<= 1) {
#pragma unroll
            for (int rh = 0; rh < 2; rh++)
#pragma unroll
                for (int hl = 0; hl < 2; hl++) {
                    ps[rh][hl] += __shfl_xor_sync(0xffffffffu, ps[rh][hl], o);
                    pd[rh][hl] += __shfl_xor_sync(0xffffffffu, pd[rh][hl], o);
                }
        }
        if (t == 0) {
            int r0 = wr * 32 + mi * 16 + g;
            s_ps[r0][2 * wc]     = ps[0][0]; s_ps[r0][2 * wc + 1]     = ps[0][1];
            s_ps[r0 + 8][2 * wc] = ps[1][0]; s_ps[r0 + 8][2 * wc + 1] = ps[1][1];
            s_pd[r0][2 * wc]     = pd[0][0]; s_pd[r0][2 * wc + 1]     = pd[0][1];
            s_pd[r0 + 8][2 * wc] = pd[1][0]; s_pd[r0 + 8][2 * wc + 1] = pd[1][1];
        }
    }
    // ---- fp16 stores: (2t,2t+1) adjacent in-lane -> direct half2 pack ----
#pragma unroll
    for (int mi = 0; mi < 2; mi++) {
        int r0 = rowBase + wr * 32 + mi * 16 + g;
#pragma unroll
        for (int ni = 0; ni < 8; ni++) {
            int cp = wc * 32 + ni * 4 + t;   // half2 column index
            if (r0 < nrows)
                d_XHh[r0 * 64 + cp] = __floats2half2_rn(acc[mi][ni][0], acc[mi][ni][1]);
            if (r0 + 8 < nrows)
                d_XHh[(r0 + 8) * 64 + cp] = __floats2half2_rn(acc[mi][ni][2], acc[mi][ni][3]);
        }
    }
    __syncthreads();
    if (tid < 128) {
        int gr = rowBase + tid;
        if (gr < nrows) {
            d_ASRC[gr] = make_float4(s_ps[tid][0], s_ps[tid][1], s_ps[tid][2], s_ps[tid][3]);
            d_ADST[gr] = make_float4(s_pd[tid][0], s_pd[tid][1], s_pd[tid][2], s_pd[tid][3]);
        }
    }
}

// ---------------- CSR build ----------------
__global__ void k_deg(const int* __restrict__ ei, int E, int N) {
    int i = blockIdx.x * blockDim.x + threadIdx.x;
    int T = E + N;
    if (i >= T) return;
    int dd = (i < E) ? ei[E + i] : (i - E);
    atomicAdd(&d_deg[dd], 1);
}

__global__ void __launch_bounds__(1024) k_scan(int N) {
    __shared__ int swarp[32];
    __shared__ int s_prev;
    int b = blockIdx.x;
    int tid = threadIdx.x, lane = tid & 31, wid = tid >> 5;
    int i = b * 1024 + tid;
    int v = (i < N) ? d_deg[i] : 0;
    int x = v;
#pragma unroll
    for (int o = 1; o < 32; o <<= 1) {
        int t = __shfl_up_sync(0xffffffffu, x, o);
        if (lane >= o) x += t;
    }
    if (lane == 31) swarp[wid] = x;
    __syncthreads();
    if (wid == 0) {
        int y = swarp[lane];
#pragma unroll
        for (int o = 1; o < 32; o <<= 1) {
            int t = __shfl_up_sync(0xffffffffu, y, o);
            if (lane >= o) y += t;
        }
        swarp[lane] = y;
    }
    __syncthreads();
    int incl = x + (wid > 0 ? swarp[wid - 1] : 0);
    int total = swarp[31];
    if (tid == 0) {
        int fv;
        while ((fv = ((volatile int*)d_flag)[b]) == 0) { }
        int prev = fv - 1;
        ((volatile int*)d_flag)[b + 1] = prev + total + 1;
        s_prev = prev;
        if (b == 0) d_rowptr[0] = 0;
    }
    __syncthreads();
    if (i < N) d_rowptr[i + 1] = s_prev + incl;
}

__global__ void k_fill(const int* __restrict__ ei, int E, int N) {
    int i = blockIdx.x * blockDim.x + threadIdx.x;
    int T = E + N;
    if (i >= T) return;
    int s, dd;
    if (i < E) { s = ei[i]; dd = ei[E + i]; }
    else       { s = dd = i - E; }
    int pos = atomicAdd(&d_cursor[dd], 1);
    d_col[d_rowptr[dd] + pos] = s;
}

// ---------------- GAT aggregation: warp per node, lane owns 4 channels (fp16 gather) ----------------
template <bool LAYER2>
__global__ void __launch_bounds__(128) k_agg(
    const float* __restrict__ bias, float* __restrict__ OUT, int N)
{
    __shared__ float4 s_e4[4][32];
    __shared__ int    s_src[4][32];

    int tid = threadIdx.x;
    int w = tid >> 5, lane = tid & 31;
    int n = blockIdx.x * 4 + w;
    if (n >= N) return;
    int h = lane >> 3;

    int start = d_rowptr[n], end = d_rowptr[n + 1];
    float4 ad = d_ADST[n];

    float m = -INFINITY, den = 0.f;
    float4 acc = make_float4(0.f, 0.f, 0.f, 0.f);
    const float* se = (const float*)&s_e4[w][0];
    const int*   ss = &s_src[w][0];
    const uint2* XH8 = (const uint2*)d_XHh;

    for (int k0 = start; k0 < end; k0 += 32) {
        int len = min(32, end - k0);
        float4 e4 = make_float4(-INFINITY, -INFINITY, -INFINITY, -INFINITY);
        int s = 0;
        if (lane < len) {
            s = __ldg(&d_col[k0 + lane]);
            float4 as = __ldg(&d_ASRC[s]);
            e4.x = as.x + ad.x; e4.x = e4.x > 0.f ? e4.x : 0.2f * e4.x;
            e4.y = as.y + ad.y; e4.y = e4.y > 0.f ? e4.y : 0.2f * e4.y;
            e4.z = as.z + ad.z; e4.z = e4.z > 0.f ? e4.z : 0.2f * e4.z;
            e4.w = as.w + ad.w; e4.w = e4.w > 0.f ? e4.w : 0.2f * e4.w;
        }
        s_src[w][lane] = s;
        s_e4[w][lane] = e4;

        float4 mx = e4;
#pragma unroll
        for (int o = 16; o >= 1; o >>= 1) {
            mx.x = fmaxf(mx.x, __shfl_xor_sync(0xffffffffu, mx.x, o));
            mx.y = fmaxf(mx.y, __shfl_xor_sync(0xffffffffu, mx.y, o));
            mx.z = fmaxf(mx.z, __shfl_xor_sync(0xffffffffu, mx.z, o));
            mx.w = fmaxf(mx.w, __shfl_xor_sync(0xffffffffu, mx.w, o));
        }
        float cmh = (h == 0) ? mx.x : (h == 1) ? mx.y : (h == 2) ? mx.z : mx.w;
        float cm = fmaxf(m, cmh);
        float scale = __expf(m - cm);
        acc.x *= scale; acc.y *= scale; acc.z *= scale; acc.w *= scale;
        den *= scale;

        __syncwarp();
#pragma unroll 4
        for (int j = 0; j < len; j++) {
            float p = __expf(se[j * 4 + h] - cm);
            den += p;
            uint2 r = __ldg(&XH8[ss[j] * 32 + lane]);
            float2 f0 = __half22float2(*(const __half2*)&r.x);
            float2 f1 = __half22float2(*(const __half2*)&r.y);
            acc.x = fmaf(p, f0.x, acc.x);
            acc.y = fmaf(p, f0.y, acc.y);
            acc.z = fmaf(p, f1.x, acc.z);
            acc.w = fmaf(p, f1.y, acc.w);
        }
        m = cm;
        __syncwarp();
    }

    float inv = 1.f / (den + 1e-16f);
    float4 val = make_float4(acc.x * inv, acc.y * inv, acc.z * inv, acc.w * inv);

    if (!LAYER2) {
        float4 b4 = ((const float4*)bias)[lane];
        val.x = fmaxf(val.x + b4.x, 0.f);
        val.y = fmaxf(val.y + b4.y, 0.f);
        val.z = fmaxf(val.z + b4.z, 0.f);
        val.w = fmaxf(val.w + b4.w, 0.f);
        ((float4*)OUT)[n * 32 + lane] = val;
    } else {
#pragma unroll
        for (int o = 8; o <= 16; o <<= 1) {
            val.x += __shfl_xor_sync(0xffffffffu, val.x, o);
            val.y += __shfl_xor_sync(0xffffffffu, val.y, o);
            val.z += __shfl_xor_sync(0xffffffffu, val.z, o);
            val.w += __shfl_xor_sync(0xffffffffu, val.w, o);
        }
        if (lane < 8) {
            float4 b4 = ((const float4*)bias)[lane];
            float4 o4 = make_float4(0.25f * val.x + b4.x, 0.25f * val.y + b4.y,
                                    0.25f * val.z + b4.z, 0.25f * val.w + b4.w);
            ((float4*)OUT)[n * 8 + lane] = o4;
        }
    }
}

// ---------------- global mean pool ----------------
__global__ void k_pool(const float* __restrict__ OUT2,
                       const int* __restrict__ batch, int N)
{
    int perBlock = (N + gridDim.x - 1) / gridDim.x;
    int n0 = blockIdx.x * perBlock;
    int n1 = min(N, n0 + perBlock);
    int ch  = threadIdx.x & 31;
    int sub = threadIdx.x >> 5;
    float sum = 0.f;
    int curb = -1;
    for (int n = n0 + sub; n < n1; n += 8) {
        int b = batch[n];
        if (b != curb) {
            if (curb >= 0) atomicAdd(&d_gsum[curb * 32 + ch], sum);
            curb = b; sum = 0.f;
        }
        sum += OUT2[n * 32 + ch];
    }
    if (curb >= 0) atomicAdd(&d_gsum[curb * 32 + ch], sum);
}

// ---------------- final MLP ----------------
__global__ void k_mlp(const int* __restrict__ batch, int N,
                      const float* __restrict__ stats,
                      const float* __restrict__ Wm1, const float* __restrict__ bm1,
                      const float* __restrict__ Wm2, const float* __restrict__ bm2,
                      float* __restrict__ out, int B)
{
    int g = threadIdx.x;
    if (g >= B) return;
    int lo0 = 0, hi0 = N;
    while (lo0 < hi0) { int mid = (lo0 + hi0) >> 1; if (batch[mid] < g) lo0 = mid + 1; else hi0 = mid; }
    int lo1 = lo0, hi1 = N;
    while (lo1 < hi1) { int mid = (lo1 + hi1) >> 1; if (batch[mid] < g + 1) lo1 = mid + 1; else hi1 = mid; }
    float cnt = (float)(lo1 - lo0);
    float inv = 1.f / fmaxf(cnt, 1.f);

    float v[47];
#pragma unroll
    for (int cc = 0; cc < 32; cc++) v[cc] = d_gsum[g * 32 + cc] * inv;
#pragma unroll
    for (int f = 0; f < 15; f++) v[32 + f] = stats[g * 15 + f];
    float o = bm2[0];
    for (int k = 0; k < 32; k++) {
        float hsum = bm1[k];
#pragma unroll
        for (int i = 0; i < 47; i++) hsum = fmaf(v[i], Wm1[i * 32 + k], hsum);
        o = fmaf(fmaxf(hsum, 0.f), Wm2[k], o);
    }
    out[g] = o;
}

// ---------------- launch ----------------
extern "C" void kernel_launch(void* const* d_in, const int* in_sizes, int n_in,
                              void* d_out, int out_size)
{
    const float* x     = (const float*)d_in[0];
    const int*   ei    = (const int*)d_in[1];
    const int*   batch = (const int*)d_in[2];
    const float* stats = (const float*)d_in[3];
    const float* W1    = (const float*)d_in[4];
    const float* as1   = (const float*)d_in[5];
    const float* ad1   = (const float*)d_in[6];
    const float* b1    = (const float*)d_in[7];
    const float* W2    = (const float*)d_in[8];
    const float* as2   = (const float*)d_in[9];
    const float* ad2   = (const float*)d_in[10];
    const float* b2    = (const float*)d_in[11];
    const float* Wm1   = (const float*)d_in[12];
    const float* bm1   = (const float*)d_in[13];
    const float* Wm2   = (const float*)d_in[14];
    const float* bm2   = (const float*)d_in[15];

    int N = in_sizes[0] / 128;
    int E = in_sizes[1] / 2;
    int B = in_sizes[3] / 15;

    float *H1, *OUT2;
    cudaGetSymbolAddress((void**)&H1,   d_H1);
    cudaGetSymbolAddress((void**)&OUT2, d_OUT2);

    int gemmBlocks = (N + 127) / 128;
    int edgeBlocks = (E + N + 255) / 256;
    int aggBlocks  = (N + 3) / 4;
    int scanBlocks = (N + 1023) / 1024;

    k_init<<<64, 256>>>(N, B);

    k_deg <<<edgeBlocks, 256>>>(ei, E, N);
    k_scan<<<scanBlocks, 1024>>>(N);
    k_fill<<<edgeBlocks, 256>>>(ei, E, N);

    k_gemm_att<<<gemmBlocks, 256>>>(x, W1, as1, ad1, N);
    k_agg<false><<<aggBlocks, 128>>>(b1, H1, N);

    k_gemm_att<<<gemmBlocks, 256>>>(H1, W2, as2, ad2, N);
    k_agg<true><<<aggBlocks, 128>>>(b2, OUT2, N);

    k_pool<<<128, 256>>>(OUT2, batch, N);
    k_mlp<<<1, 128>>>(batch, N, stats, Wm1, bm1, Wm2, bm2, (float*)d_out, B);
}

// round 8
// speedup vs baseline: 2.5228x; 1.1628x over previous
#include <cuda_runtime.h>
#include <cuda_fp16.h>
#include <stdint.h>
#include <math.h>

#define NMAX 50000
#define EMAX 800000
#define BMAX 128

// ---------------- scratch ----------------
__device__ __half2 d_XHh [NMAX * 64];    // GEMM output fp16 (128 ch = 64 half2/node)
__device__ __half2 d_H1h [NMAX * 64];    // layer-1 output fp16
__device__ __half  d_Wt1 [128 * 128];    // W1^T fp16  [n][k]
__device__ __half  d_Wt2 [128 * 128];    // W2^T fp16  [n][k]
__device__ float   d_OUT2[NMAX * 32];
__device__ float   d_ASRC[NMAX * 4];
__device__ float   d_ADST[NMAX * 4];
__device__ int     d_deg   [NMAX];
__device__ int     d_rowptr[NMAX + 1];
__device__ int     d_cursor[NMAX];
__device__ int     d_col   [EMAX + NMAX];
__device__ float   d_gsum  [BMAX * 32];
__device__ int     d_flag  [64];

// ---------------- init ----------------
__global__ void k_init(int N, int B) {
    int i0 = blockIdx.x * blockDim.x + threadIdx.x;
    int stride = gridDim.x * blockDim.x;
    for (int t = i0; t < N; t += stride) d_deg[t] = 1;   // self loop pre-counted
    for (int t = i0; t < B * 32; t += stride) d_gsum[t] = 0.f;
    for (int t = i0; t < 64; t += stride) d_flag[t] = (t == 0) ? 1 : 0;
}

// ---------------- weight prep: W[k][n] fp32 -> Wt[n][k] fp16 ----------------
__global__ void k_prep(const float* __restrict__ W1, const float* __restrict__ W2) {
    int i = blockIdx.x * blockDim.x + threadIdx.x;   // 16384 per matrix
    if (i < 16384) {
        int n = i >> 7, k = i & 127;
        d_Wt1[n * 128 + k] = __float2half_rn(W1[k * 128 + n]);
    } else if (i < 32768) {
        int j = i - 16384;
        int n = j >> 7, k = j & 127;
        d_Wt2[n * 128 + k] = __float2half_rn(W2[k * 128 + n]);
    }
}

// ---------------- tensor-core GEMM + fused attention dots ----------------
// k-tile 32 -> 20.5KB smem -> 2 CTAs/SM. Dots stored direct to global (owner-unique).
template <bool HIN>
__global__ void __launch_bounds__(256, 2) k_gemm_att(
    const void* __restrict__ Xv, const __half* __restrict__ Wt,
    const float* __restrict__ att_s, const float* __restrict__ att_d,
    int nrows)
{
    __shared__ __half Xs[128][40];
    __shared__ __half Ws[128][40];

    int tid = threadIdx.x;
    int wid = tid >> 5, lane = tid & 31;
    int g = lane >> 2, t = lane & 3;
    int wr = wid >> 1, wc = wid & 1;
    int rowBase = blockIdx.x * 128;

    float acc[2][8][4];
#pragma unroll
    for (int mi = 0; mi < 2; mi++)
#pragma unroll
        for (int ni = 0; ni < 8; ni++)
#pragma unroll
            for (int q = 0; q < 4; q++) acc[mi][ni][q] = 0.f;

    for (int k0 = 0; k0 < 128; k0 += 32) {
        // X tile: 128 rows x 32 k
        if (HIN) {
            const uint4* Xh = (const uint4*)Xv;   // fp16 rows: 128 ch = 16 uint4
#pragma unroll
            for (int it = 0; it < 2; it++) {
                int idx = tid + 256 * it;          // 512 uint4
                int r = idx >> 2;
                int c8 = (idx & 3) * 8;            // half index
                int gr = rowBase + r;
                uint4 v = (gr < nrows) ? Xh[gr * 16 + (k0 >> 3) + (c8 >> 3)]
                                       : make_uint4(0u, 0u, 0u, 0u);
                *(uint4*)&Xs[r][c8] = v;
            }
        } else {
            const float* X = (const float*)Xv;
#pragma unroll
            for (int it = 0; it < 4; it++) {
                int idx = tid + 256 * it;          // 1024 float4
                int r = idx >> 3;
                int c4 = (idx & 7) * 4;
                int gr = rowBase + r;
                float4 v = (gr < nrows) ? *(const float4*)&X[gr * 128 + k0 + c4]
                                        : make_float4(0.f, 0.f, 0.f, 0.f);
                __half2 h0 = __floats2half2_rn(v.x, v.y);
                __half2 h1 = __floats2half2_rn(v.z, v.w);
                uint2 p; p.x = *(uint32_t*)&h0; p.y = *(uint32_t*)&h1;
                *(uint2*)&Xs[r][c4] = p;
            }
        }
        // W tile: 128 n-rows x 32 k (fp16 global, direct copy)
#pragma unroll
        for (int it = 0; it < 2; it++) {
            int idx = tid + 256 * it;
            int n = idx >> 2;
            int c8 = (idx & 3) * 8;
            *(uint4*)&Ws[n][c8] = *(const uint4*)&Wt[n * 128 + k0 + c8];
        }
        __syncthreads();
#pragma unroll
        for (int ks = 0; ks < 2; ks++) {
            int kb = ks * 16;
            uint32_t a[2][4];
#pragma unroll
            for (int mi = 0; mi < 2; mi++) {
                int ar = wr * 32 + mi * 16 + g;
                a[mi][0] = *(const uint32_t*)&Xs[ar][kb + 2 * t];
                a[mi][1] = *(const uint32_t*)&Xs[ar + 8][kb + 2 * t];
                a[mi][2] = *(const uint32_t*)&Xs[ar][kb + 2 * t + 8];
                a[mi][3] = *(const uint32_t*)&Xs[ar + 8][kb + 2 * t + 8];
            }
#pragma unroll
            for (int ni = 0; ni < 8; ni++) {
                int bn = wc * 64 + ni * 8 + g;
                uint32_t b0 = *(const uint32_t*)&Ws[bn][kb + 2 * t];
                uint32_t b1 = *(const uint32_t*)&Ws[bn][kb + 2 * t + 8];
#pragma unroll
                for (int mi = 0; mi < 2; mi++) {
                    asm volatile(
                        "mma.sync.aligned.m16n8k16.row.col.f32.f16.f16.f32 "
                        "{%0,%1,%2,%3}, {%4,%5,%6,%7}, {%8,%9}, {%0,%1,%2,%3};"
                        : "+f"(acc[mi][ni][0]), "+f"(acc[mi][ni][1]),
                          "+f"(acc[mi][ni][2]), "+f"(acc[mi][ni][3])
                        : "r"(a[mi][0]), "r"(a[mi][1]), "r"(a[mi][2]), "r"(a[mi][3]),
                          "r"(b0), "r"(b1));
                }
            }
        }
        __syncthreads();
    }

    // ---- epilogue: attention dots, direct global store (owner-unique (row,head)) ----
#pragma unroll
    for (int mi = 0; mi < 2; mi++) {
        float ps[2][2] = {{0.f, 0.f}, {0.f, 0.f}};
        float pd[2][2] = {{0.f, 0.f}, {0.f, 0.f}};
#pragma unroll
        for (int ni = 0; ni < 8; ni++) {
            int col = wc * 64 + ni * 8 + 2 * t;
            float s0 = att_s[col], s1 = att_s[col + 1];
            float dd0 = att_d[col], dd1 = att_d[col + 1];
            int hl = ni >> 2;
            ps[0][hl] += acc[mi][ni][0] * s0 + acc[mi][ni][1] * s1;
            ps[1][hl] += acc[mi][ni][2] * s0 + acc[mi][ni][3] * s1;
            pd[0][hl] += acc[mi][ni][0] * dd0 + acc[mi][ni][1] * dd1;
            pd[1][hl] += acc[mi][ni][2] * dd0 + acc[mi][ni][3] * dd1;
        }
#pragma unroll
        for (int o = 1; o <= 2; o <<= 1) {
#pragma unroll
            for (int rh = 0; rh < 2; rh++)
#pragma unroll
                for (int hl = 0; hl < 2; hl++) {
                    ps[rh][hl] += __shfl_xor_sync(0xffffffffu, ps[rh][hl], o);
                    pd[rh][hl] += __shfl_xor_sync(0xffffffffu, pd[rh][hl], o);
                }
        }
        if (t == 0) {
            int gr = rowBase + wr * 32 + mi * 16 + g;
            if (gr < nrows) {
                d_ASRC[gr * 4 + 2 * wc]     = ps[0][0];
                d_ASRC[gr * 4 + 2 * wc + 1] = ps[0][1];
                d_ADST[gr * 4 + 2 * wc]     = pd[0][0];
                d_ADST[gr * 4 + 2 * wc + 1] = pd[0][1];
            }
            if (gr + 8 < nrows) {
                d_ASRC[(gr + 8) * 4 + 2 * wc]     = ps[1][0];
                d_ASRC[(gr + 8) * 4 + 2 * wc + 1] = ps[1][1];
                d_ADST[(gr + 8) * 4 + 2 * wc]     = pd[1][0];
                d_ADST[(gr + 8) * 4 + 2 * wc + 1] = pd[1][1];
            }
        }
    }
    // ---- fp16 XH stores ----
#pragma unroll
    for (int mi = 0; mi < 2; mi++) {
        int r0 = rowBase + wr * 32 + mi * 16 + g;
#pragma unroll
        for (int ni = 0; ni < 8; ni++) {
            int cp = wc * 32 + ni * 4 + t;
            if (r0 < nrows)
                d_XHh[r0 * 64 + cp] = __floats2half2_rn(acc[mi][ni][0], acc[mi][ni][1]);
            if (r0 + 8 < nrows)
                d_XHh[(r0 + 8) * 64 + cp] = __floats2half2_rn(acc[mi][ni][2], acc[mi][ni][3]);
        }
    }
}

// ---------------- CSR build ----------------
__global__ void k_deg(const int* __restrict__ ei, int E) {
    int i = blockIdx.x * blockDim.x + threadIdx.x;
    if (i >= E) return;
    atomicAdd(&d_deg[ei[E + i]], 1);
}

__global__ void __launch_bounds__(1024) k_scan(int N) {
    __shared__ int swarp[32];
    __shared__ int s_prev;
    int b = blockIdx.x;
    int tid = threadIdx.x, lane = tid & 31, wid = tid >> 5;
    int i = b * 1024 + tid;
    int v = (i < N) ? d_deg[i] : 0;
    int x = v;
#pragma unroll
    for (int o = 1; o < 32; o <<= 1) {
        int t = __shfl_up_sync(0xffffffffu, x, o);
        if (lane >= o) x += t;
    }
    if (lane == 31) swarp[wid] = x;
    __syncthreads();
    if (wid == 0) {
        int y = swarp[lane];
#pragma unroll
        for (int o = 1; o < 32; o <<= 1) {
            int t = __shfl_up_sync(0xffffffffu, y, o);
            if (lane >= o) y += t;
        }
        swarp[lane] = y;
    }
    __syncthreads();
    int incl = x + (wid > 0 ? swarp[wid - 1] : 0);
    int total = swarp[31];
    if (tid == 0) {
        int fv;
        while ((fv = ((volatile int*)d_flag)[b]) == 0) { }
        int prev = fv - 1;
        ((volatile int*)d_flag)[b + 1] = prev + total + 1;
        s_prev = prev;
        if (b == 0) d_rowptr[0] = 0;
    }
    __syncthreads();
    if (i < N) {
        d_rowptr[i + 1] = s_prev + incl;
        d_cursor[i] = s_prev + incl - v;   // row start: fill uses single atomic
    }
}

// edges via cursor atomic (absolute position); self loop takes guaranteed-last slot
__global__ void k_fill(const int* __restrict__ ei, int E, int N) {
    int i = blockIdx.x * blockDim.x + threadIdx.x;
    int T = E + N;
    if (i >= T) return;
    if (i < E) {
        int s = ei[i], dd = ei[E + i];
        int pos = atomicAdd(&d_cursor[dd], 1);
        d_col[pos] = s;
    } else {
        int n = i - E;
        d_col[d_rowptr[n + 1] - 1] = n;
    }
}

// ---------------- GAT aggregation: warp per node, lane owns 4 channels ----------------
template <bool LAYER2>
__global__ void __launch_bounds__(128) k_agg(
    const float* __restrict__ bias, void* __restrict__ OUT, int N)
{
    __shared__ float4 s_e4[4][32];
    __shared__ int    s_src[4][32];

    int tid = threadIdx.x;
    int w = tid >> 5, lane = tid & 31;
    int n = blockIdx.x * 4 + w;
    if (n >= N) return;
    int h = lane >> 3;

    int start = d_rowptr[n], end = d_rowptr[n + 1];
    float4 ad = ((const float4*)d_ADST)[n];

    float m = -INFINITY, den = 0.f;
    float4 acc = make_float4(0.f, 0.f, 0.f, 0.f);
    const float* se = (const float*)&s_e4[w][0];
    const int*   ss = &s_src[w][0];
    const uint2* XH8 = (const uint2*)d_XHh;

    for (int k0 = start; k0 < end; k0 += 32) {
        int len = min(32, end - k0);
        float4 e4 = make_float4(-INFINITY, -INFINITY, -INFINITY, -INFINITY);
        int s = 0;
        if (lane < len) {
            s = __ldg(&d_col[k0 + lane]);
            float4 as = __ldg(&((const float4*)d_ASRC)[s]);
            e4.x = as.x + ad.x; e4.x = e4.x > 0.f ? e4.x : 0.2f * e4.x;
            e4.y = as.y + ad.y; e4.y = e4.y > 0.f ? e4.y : 0.2f * e4.y;
            e4.z = as.z + ad.z; e4.z = e4.z > 0.f ? e4.z : 0.2f * e4.z;
            e4.w = as.w + ad.w; e4.w = e4.w > 0.f ? e4.w : 0.2f * e4.w;
        }
        s_src[w][lane] = s;
        s_e4[w][lane] = e4;

        float4 mx = e4;
#pragma unroll
        for (int o = 16; o >= 1; o >>= 1) {
            mx.x = fmaxf(mx.x, __shfl_xor_sync(0xffffffffu, mx.x, o));
            mx.y = fmaxf(mx.y, __shfl_xor_sync(0xffffffffu, mx.y, o));
            mx.z = fmaxf(mx.z, __shfl_xor_sync(0xffffffffu, mx.z, o));
            mx.w = fmaxf(mx.w, __shfl_xor_sync(0xffffffffu, mx.w, o));
        }
        float cmh = (h == 0) ? mx.x : (h == 1) ? mx.y : (h == 2) ? mx.z : mx.w;
        float cm = fmaxf(m, cmh);
        float scale = __expf(m - cm);
        acc.x *= scale; acc.y *= scale; acc.z *= scale; acc.w *= scale;
        den *= scale;

        __syncwarp();
#pragma unroll 4
        for (int j = 0; j < len; j++) {
            float p = __expf(se[j * 4 + h] - cm);
            den += p;
            uint2 r = __ldg(&XH8[ss[j] * 32 + lane]);
            float2 f0 = __half22float2(*(const __half2*)&r.x);
            float2 f1 = __half22float2(*(const __half2*)&r.y);
            acc.x = fmaf(p, f0.x, acc.x);
            acc.y = fmaf(p, f0.y, acc.y);
            acc.z = fmaf(p, f1.x, acc.z);
            acc.w = fmaf(p, f1.y, acc.w);
        }
        m = cm;
        __syncwarp();
    }

    float inv = 1.f / (den + 1e-16f);
    float4 val = make_float4(acc.x * inv, acc.y * inv, acc.z * inv, acc.w * inv);

    if (!LAYER2) {
        float4 b4 = ((const float4*)bias)[lane];
        val.x = fmaxf(val.x + b4.x, 0.f);
        val.y = fmaxf(val.y + b4.y, 0.f);
        val.z = fmaxf(val.z + b4.z, 0.f);
        val.w = fmaxf(val.w + b4.w, 0.f);
        __half2 h0 = __floats2half2_rn(val.x, val.y);
        __half2 h1 = __floats2half2_rn(val.z, val.w);
        uint2 p; p.x = *(uint32_t*)&h0; p.y = *(uint32_t*)&h1;
        ((uint2*)OUT)[n * 32 + lane] = p;     // fp16 H1
    } else {
#pragma unroll
        for (int o = 8; o <= 16; o <<= 1) {
            val.x += __shfl_xor_sync(0xffffffffu, val.x, o);
            val.y += __shfl_xor_sync(0xffffffffu, val.y, o);
            val.z += __shfl_xor_sync(0xffffffffu, val.z, o);
            val.w += __shfl_xor_sync(0xffffffffu, val.w, o);
        }
        if (lane < 8) {
            float4 b4 = ((const float4*)bias)[lane];
            float4 o4 = make_float4(0.25f * val.x + b4.x, 0.25f * val.y + b4.y,
                                    0.25f * val.z + b4.z, 0.25f * val.w + b4.w);
            ((float4*)OUT)[n * 8 + lane] = o4;
        }
    }
}

// ---------------- global mean pool ----------------
__global__ void k_pool(const float* __restrict__ OUT2,
                       const int* __restrict__ batch, int N)
{
    int perBlock = (N + gridDim.x - 1) / gridDim.x;
    int n0 = blockIdx.x * perBlock;
    int n1 = min(N, n0 + perBlock);
    int ch  = threadIdx.x & 31;
    int sub = threadIdx.x >> 5;
    float sum = 0.f;
    int curb = -1;
    for (int n = n0 + sub; n < n1; n += 8) {
        int b = batch[n];
        if (b != curb) {
            if (curb >= 0) atomicAdd(&d_gsum[curb * 32 + ch], sum);
            curb = b; sum = 0.f;
        }
        sum += OUT2[n * 32 + ch];
    }
    if (curb >= 0) atomicAdd(&d_gsum[curb * 32 + ch], sum);
}

// ---------------- final MLP ----------------
__global__ void k_mlp(const int* __restrict__ batch, int N,
                      const float* __restrict__ stats,
                      const float* __restrict__ Wm1, const float* __restrict__ bm1,
                      const float* __restrict__ Wm2, const float* __restrict__ bm2,
                      float* __restrict__ out, int B)
{
    int g = threadIdx.x;
    if (g >= B) return;
    int lo0 = 0, hi0 = N;
    while (lo0 < hi0) { int mid = (lo0 + hi0) >> 1; if (batch[mid] < g) lo0 = mid + 1; else hi0 = mid; }
    int lo1 = lo0, hi1 = N;
    while (lo1 < hi1) { int mid = (lo1 + hi1) >> 1; if (batch[mid] < g + 1) lo1 = mid + 1; else hi1 = mid; }
    float cnt = (float)(lo1 - lo0);
    float inv = 1.f / fmaxf(cnt, 1.f);

    float v[47];
#pragma unroll
    for (int cc = 0; cc < 32; cc++) v[cc] = d_gsum[g * 32 + cc] * inv;
#pragma unroll
    for (int f = 0; f < 15; f++) v[32 + f] = stats[g * 15 + f];
    float o = bm2[0];
    for (int k = 0; k < 32; k++) {
        float hsum = bm1[k];
#pragma unroll
        for (int i = 0; i < 47; i++) hsum = fmaf(v[i], Wm1[i * 32 + k], hsum);
        o = fmaf(fmaxf(hsum, 0.f), Wm2[k], o);
    }
    out[g] = o;
}

// ---------------- launch ----------------
extern "C" void kernel_launch(void* const* d_in, const int* in_sizes, int n_in,
                              void* d_out, int out_size)
{
    const float* x     = (const float*)d_in[0];
    const int*   ei    = (const int*)d_in[1];
    const int*   batch = (const int*)d_in[2];
    const float* stats = (const float*)d_in[3];
    const float* W1    = (const float*)d_in[4];
    const float* as1   = (const float*)d_in[5];
    const float* ad1   = (const float*)d_in[6];
    const float* b1    = (const float*)d_in[7];
    const float* W2    = (const float*)d_in[8];
    const float* as2   = (const float*)d_in[9];
    const float* ad2   = (const float*)d_in[10];
    const float* b2    = (const float*)d_in[11];
    const float* Wm1   = (const float*)d_in[12];
    const float* bm1   = (const float*)d_in[13];
    const float* Wm2   = (const float*)d_in[14];
    const float* bm2   = (const float*)d_in[15];

    int N = in_sizes[0] / 128;
    int E = in_sizes[1] / 2;
    int B = in_sizes[3] / 15;

    __half *Wt1, *Wt2; __half2 *H1h; float *OUT2;
    cudaGetSymbolAddress((void**)&Wt1,  d_Wt1);
    cudaGetSymbolAddress((void**)&Wt2,  d_Wt2);
    cudaGetSymbolAddress((void**)&H1h,  d_H1h);
    cudaGetSymbolAddress((void**)&OUT2, d_OUT2);

    int gemmBlocks = (N + 127) / 128;
    int edgeBlocks = (E + 255) / 256;
    int fillBlocks = (E + N + 255) / 256;
    int aggBlocks  = (N + 3) / 4;
    int scanBlocks = (N + 1023) / 1024;

    k_init<<<64, 256>>>(N, B);
    k_prep<<<128, 256>>>(W1, W2);

    k_deg <<<edgeBlocks, 256>>>(ei, E);
    k_scan<<<scanBlocks, 1024>>>(N);
    k_fill<<<fillBlocks, 256>>>(ei, E, N);

    k_gemm_att<false><<<gemmBlocks, 256>>>(x, Wt1, as1, ad1, N);
    k_agg<false><<<aggBlocks, 128>>>(b1, H1h, N);

    k_gemm_att<true><<<gemmBlocks, 256>>>(H1h, Wt2, as2, ad2, N);
    k_agg<true><<<aggBlocks, 128>>>(b2, OUT2, N);

    k_pool<<<128, 256>>>(OUT2, batch, N);
    k_mlp<<<1, 128>>>(batch, N, stats, Wm1, bm1, Wm2, bm2, (float*)d_out, B);
}

// round 9
// speedup vs baseline: 2.7040x; 1.0718x over previous
#include <cuda_runtime.h>
#include <cuda_fp16.h>
#include <stdint.h>
#include <math.h>

#define NMAX 50000
#define EMAX 800000
#define BMAX 128

// ---------------- scratch ----------------
__device__ __half2 d_XHh [NMAX * 64];    // GEMM output fp16 (128 ch = 64 half2/node)
__device__ __half2 d_H1h [NMAX * 64];    // layer-1 output fp16
__device__ __half  d_Wt1 [128 * 128];    // W1^T fp16  [n][k]
__device__ __half  d_Wt2 [128 * 128];    // W2^T fp16  [n][k]
__device__ float   d_OUT2[NMAX * 32];
__device__ float   d_ASRC[NMAX * 4];
__device__ float   d_ADST[NMAX * 4];
__device__ int     d_deg   [NMAX];
__device__ int     d_rowptr[NMAX + 1];
__device__ int     d_cursor[NMAX];
__device__ int     d_col   [EMAX + NMAX];
__device__ float   d_gsum  [BMAX * 32];
__device__ int     d_bsum  [64];
__device__ int     d_boff  [64];

// ---------------- init ----------------
__global__ void k_init(int N, int B) {
    int i0 = blockIdx.x * blockDim.x + threadIdx.x;
    int stride = gridDim.x * blockDim.x;
    for (int t = i0; t < N; t += stride) d_deg[t] = 1;   // self loop pre-counted
    for (int t = i0; t < B * 32; t += stride) d_gsum[t] = 0.f;
}

// ---------------- weight prep: W[k][n] fp32 -> Wt[n][k] fp16 ----------------
__global__ void k_prep(const float* __restrict__ W1, const float* __restrict__ W2) {
    int i = blockIdx.x * blockDim.x + threadIdx.x;
    if (i < 16384) {
        int n = i >> 7, k = i & 127;
        d_Wt1[n * 128 + k] = __float2half_rn(W1[k * 128 + n]);
    } else if (i < 32768) {
        int j = i - 16384;
        int n = j >> 7, k = j & 127;
        d_Wt2[n * 128 + k] = __float2half_rn(W2[k * 128 + n]);
    }
}

// ---------------- tensor-core GEMM + fused attention dots ----------------
template <bool HIN>
__global__ void __launch_bounds__(256, 2) k_gemm_att(
    const void* __restrict__ Xv, const __half* __restrict__ Wt,
    const float* __restrict__ att_s, const float* __restrict__ att_d,
    int nrows)
{
    __shared__ __half Xs[128][40];
    __shared__ __half Ws[128][40];

    int tid = threadIdx.x;
    int wid = tid >> 5, lane = tid & 31;
    int g = lane >> 2, t = lane & 3;
    int wr = wid >> 1, wc = wid & 1;
    int rowBase = blockIdx.x * 128;

    float acc[2][8][4];
#pragma unroll
    for (int mi = 0; mi < 2; mi++)
#pragma unroll
        for (int ni = 0; ni < 8; ni++)
#pragma unroll
            for (int q = 0; q < 4; q++) acc[mi][ni][q] = 0.f;

    for (int k0 = 0; k0 < 128; k0 += 32) {
        if (HIN) {
            const uint4* Xh = (const uint4*)Xv;
#pragma unroll
            for (int it = 0; it < 2; it++) {
                int idx = tid + 256 * it;
                int r = idx >> 2;
                int c8 = (idx & 3) * 8;
                int gr = rowBase + r;
                uint4 v = (gr < nrows) ? Xh[gr * 16 + (k0 >> 3) + (c8 >> 3)]
                                       : make_uint4(0u, 0u, 0u, 0u);
                *(uint4*)&Xs[r][c8] = v;
            }
        } else {
            const float* X = (const float*)Xv;
#pragma unroll
            for (int it = 0; it < 4; it++) {
                int idx = tid + 256 * it;
                int r = idx >> 3;
                int c4 = (idx & 7) * 4;
                int gr = rowBase + r;
                float4 v = (gr < nrows) ? *(const float4*)&X[gr * 128 + k0 + c4]
                                        : make_float4(0.f, 0.f, 0.f, 0.f);
                __half2 h0 = __floats2half2_rn(v.x, v.y);
                __half2 h1 = __floats2half2_rn(v.z, v.w);
                uint2 p; p.x = *(uint32_t*)&h0; p.y = *(uint32_t*)&h1;
                *(uint2*)&Xs[r][c4] = p;
            }
        }
#pragma unroll
        for (int it = 0; it < 2; it++) {
            int idx = tid + 256 * it;
            int n = idx >> 2;
            int c8 = (idx & 3) * 8;
            *(uint4*)&Ws[n][c8] = *(const uint4*)&Wt[n * 128 + k0 + c8];
        }
        __syncthreads();
#pragma unroll
        for (int ks = 0; ks < 2; ks++) {
            int kb = ks * 16;
            uint32_t a[2][4];
#pragma unroll
            for (int mi = 0; mi < 2; mi++) {
                int ar = wr * 32 + mi * 16 + g;
                a[mi][0] = *(const uint32_t*)&Xs[ar][kb + 2 * t];
                a[mi][1] = *(const uint32_t*)&Xs[ar + 8][kb + 2 * t];
                a[mi][2] = *(const uint32_t*)&Xs[ar][kb + 2 * t + 8];
                a[mi][3] = *(const uint32_t*)&Xs[ar + 8][kb + 2 * t + 8];
            }
#pragma unroll
            for (int ni = 0; ni < 8; ni++) {
                int bn = wc * 64 + ni * 8 + g;
                uint32_t b0 = *(const uint32_t*)&Ws[bn][kb + 2 * t];
                uint32_t b1 = *(const uint32_t*)&Ws[bn][kb + 2 * t + 8];
#pragma unroll
                for (int mi = 0; mi < 2; mi++) {
                    asm volatile(
                        "mma.sync.aligned.m16n8k16.row.col.f32.f16.f16.f32 "
                        "{%0,%1,%2,%3}, {%4,%5,%6,%7}, {%8,%9}, {%0,%1,%2,%3};"
                        : "+f"(acc[mi][ni][0]), "+f"(acc[mi][ni][1]),
                          "+f"(acc[mi][ni][2]), "+f"(acc[mi][ni][3])
                        : "r"(a[mi][0]), "r"(a[mi][1]), "r"(a[mi][2]), "r"(a[mi][3]),
                          "r"(b0), "r"(b1));
                }
            }
        }
        __syncthreads();
    }

    // ---- epilogue: attention dots, direct global store ----
#pragma unroll
    for (int mi = 0; mi < 2; mi++) {
        float ps[2][2] = {{0.f, 0.f}, {0.f, 0.f}};
        float pd[2][2] = {{0.f, 0.f}, {0.f, 0.f}};
#pragma unroll
        for (int ni = 0; ni < 8; ni++) {
            int col = wc * 64 + ni * 8 + 2 * t;
            float s0 = att_s[col], s1 = att_s[col + 1];
            float dd0 = att_d[col], dd1 = att_d[col + 1];
            int hl = ni >> 2;
            ps[0][hl] += acc[mi][ni][0] * s0 + acc[mi][ni][1] * s1;
            ps[1][hl] += acc[mi][ni][2] * s0 + acc[mi][ni][3] * s1;
            pd[0][hl] += acc[mi][ni][0] * dd0 + acc[mi][ni][1] * dd1;
            pd[1][hl] += acc[mi][ni][2] * dd0 + acc[mi][ni][3] * dd1;
        }
#pragma unroll
        for (int o = 1; o <= 2; o <<= 1) {
#pragma unroll
            for (int rh = 0; rh < 2; rh++)
#pragma unroll
                for (int hl = 0; hl < 2; hl++) {
                    ps[rh][hl] += __shfl_xor_sync(0xffffffffu, ps[rh][hl], o);
                    pd[rh][hl] += __shfl_xor_sync(0xffffffffu, pd[rh][hl], o);
                }
        }
        if (t == 0) {
            int gr = rowBase + wr * 32 + mi * 16 + g;
            if (gr < nrows) {
                d_ASRC[gr * 4 + 2 * wc]     = ps[0][0];
                d_ASRC[gr * 4 + 2 * wc + 1] = ps[0][1];
                d_ADST[gr * 4 + 2 * wc]     = pd[0][0];
                d_ADST[gr * 4 + 2 * wc + 1] = pd[0][1];
            }
            if (gr + 8 < nrows) {
                d_ASRC[(gr + 8) * 4 + 2 * wc]     = ps[1][0];
                d_ASRC[(gr + 8) * 4 + 2 * wc + 1] = ps[1][1];
                d_ADST[(gr + 8) * 4 + 2 * wc]     = pd[1][0];
                d_ADST[(gr + 8) * 4 + 2 * wc + 1] = pd[1][1];
            }
        }
    }
#pragma unroll
    for (int mi = 0; mi < 2; mi++) {
        int r0 = rowBase + wr * 32 + mi * 16 + g;
#pragma unroll
        for (int ni = 0; ni < 8; ni++) {
            int cp = wc * 32 + ni * 4 + t;
            if (r0 < nrows)
                d_XHh[r0 * 64 + cp] = __floats2half2_rn(acc[mi][ni][0], acc[mi][ni][1]);
            if (r0 + 8 < nrows)
                d_XHh[(r0 + 8) * 64 + cp] = __floats2half2_rn(acc[mi][ni][2], acc[mi][ni][3]);
        }
    }
}

// ---------------- CSR build ----------------
__global__ void k_deg(const int* __restrict__ ei, int E) {
    int i = blockIdx.x * blockDim.x + threadIdx.x;
    if (i >= E) return;
    atomicAdd(&d_deg[ei[E + i]], 1);
}

// ---- 3-phase reduce-then-scan (no inter-block chaining) ----
// phase 1: block-local inclusive scan -> rowptr[i+1] (pre-offset), block total -> d_bsum
__global__ void __launch_bounds__(1024) k_scan1(int N) {
    __shared__ int swarp[32];
    int b = blockIdx.x;
    int tid = threadIdx.x, lane = tid & 31, wid = tid >> 5;
    int i = b * 1024 + tid;
    int v = (i < N) ? d_deg[i] : 0;
    int x = v;
#pragma unroll
    for (int o = 1; o < 32; o <<= 1) {
        int t = __shfl_up_sync(0xffffffffu, x, o);
        if (lane >= o) x += t;
    }
    if (lane == 31) swarp[wid] = x;
    __syncthreads();
    if (wid == 0) {
        int y = swarp[lane];
#pragma unroll
        for (int o = 1; o < 32; o <<= 1) {
            int t = __shfl_up_sync(0xffffffffu, y, o);
            if (lane >= o) y += t;
        }
        swarp[lane] = y;
    }
    __syncthreads();
    int incl = x + (wid > 0 ? swarp[wid - 1] : 0);
    if (i < N) d_rowptr[i + 1] = incl;
    if (tid == 1023) d_bsum[b] = incl;
}

// phase 2: one block scans the <=64 block totals (exclusive)
__global__ void k_scan2(int nb) {
    int lane = threadIdx.x;   // 64 threads, 2 warps
    __shared__ int s_w0;
    int v = (lane < nb) ? d_bsum[lane] : 0;
    int x = v;
#pragma unroll
    for (int o = 1; o < 32; o <<= 1) {
        int t = __shfl_up_sync(0xffffffffu, x, o);
        if ((lane & 31) >= o) x += t;
    }
    if (lane == 31) s_w0 = x;
    __syncthreads();
    int excl = x - v + ((lane >= 32) ? s_w0 : 0);
    if (lane < nb) d_boff[lane] = excl;
}

// phase 3: add block offset; emit final rowptr + cursor (row start)
__global__ void __launch_bounds__(1024) k_scan3(int N) {
    int b = blockIdx.x;
    int i = b * 1024 + threadIdx.x;
    if (i >= N) return;
    int off = d_boff[b];
    int rp = d_rowptr[i + 1] + off;
    d_rowptr[i + 1] = rp;
    d_cursor[i] = rp - d_deg[i];
    if (i == 0) d_rowptr[0] = 0;
}

// edges via cursor atomic; self loop takes guaranteed-last slot (no atomic)
__global__ void k_fill(const int* __restrict__ ei, int E, int N) {
    int i = blockIdx.x * blockDim.x + threadIdx.x;
    int T = E + N;
    if (i >= T) return;
    if (i < E) {
        int s = ei[i], dd = ei[E + i];
        int pos = atomicAdd(&d_cursor[dd], 1);
        d_col[pos] = s;
    } else {
        int n = i - E;
        d_col[d_rowptr[n + 1] - 1] = n;
    }
}

// ---------------- GAT aggregation: warp per node, lane owns 4 channels ----------------
template <bool LAYER2>
__global__ void __launch_bounds__(128) k_agg(
    const float* __restrict__ bias, void* __restrict__ OUT, int N)
{
    __shared__ float4 s_e4[4][32];
    __shared__ int    s_src[4][32];

    int tid = threadIdx.x;
    int w = tid >> 5, lane = tid & 31;
    int n = blockIdx.x * 4 + w;
    if (n >= N) return;
    int h = lane >> 3;

    int start = d_rowptr[n], end = d_rowptr[n + 1];
    float4 ad = ((const float4*)d_ADST)[n];

    float m = -INFINITY, den = 0.f;
    float4 acc = make_float4(0.f, 0.f, 0.f, 0.f);
    const float* se = (const float*)&s_e4[w][0];
    const int*   ss = &s_src[w][0];
    const uint2* XH8 = (const uint2*)d_XHh;

    for (int k0 = start; k0 < end; k0 += 32) {
        int len = min(32, end - k0);
        float4 e4 = make_float4(-INFINITY, -INFINITY, -INFINITY, -INFINITY);
        int s = 0;
        if (lane < len) {
            s = __ldg(&d_col[k0 + lane]);
            float4 as = __ldg(&((const float4*)d_ASRC)[s]);
            e4.x = as.x + ad.x; e4.x = e4.x > 0.f ? e4.x : 0.2f * e4.x;
            e4.y = as.y + ad.y; e4.y = e4.y > 0.f ? e4.y : 0.2f * e4.y;
            e4.z = as.z + ad.z; e4.z = e4.z > 0.f ? e4.z : 0.2f * e4.z;
            e4.w = as.w + ad.w; e4.w = e4.w > 0.f ? e4.w : 0.2f * e4.w;
        }
        s_src[w][lane] = s;
        s_e4[w][lane] = e4;

        float4 mx = e4;
#pragma unroll
        for (int o = 16; o >= 1; o >>= 1) {
            mx.x = fmaxf(mx.x, __shfl_xor_sync(0xffffffffu, mx.x, o));
            mx.y = fmaxf(mx.y, __shfl_xor_sync(0xffffffffu, mx.y, o));
            mx.z = fmaxf(mx.z, __shfl_xor_sync(0xffffffffu, mx.z, o));
            mx.w = fmaxf(mx.w, __shfl_xor_sync(0xffffffffu, mx.w, o));
        }
        float cmh = (h == 0) ? mx.x : (h == 1) ? mx.y : (h == 2) ? mx.z : mx.w;
        float cm = fmaxf(m, cmh);
        float scale = __expf(m - cm);
        acc.x *= scale; acc.y *= scale; acc.z *= scale; acc.w *= scale;
        den *= scale;

        __syncwarp();
#pragma unroll 4
        for (int j = 0; j < len; j++) {
            float p = __expf(se[j * 4 + h] - cm);
            den += p;
            uint2 r = __ldg(&XH8[ss[j] * 32 + lane]);
            float2 f0 = __half22float2(*(const __half2*)&r.x);
            float2 f1 = __half22float2(*(const __half2*)&r.y);
            acc.x = fmaf(p, f0.x, acc.x);
            acc.y = fmaf(p, f0.y, acc.y);
            acc.z = fmaf(p, f1.x, acc.z);
            acc.w = fmaf(p, f1.y, acc.w);
        }
        m = cm;
        __syncwarp();
    }

    float inv = 1.f / (den + 1e-16f);
    float4 val = make_float4(acc.x * inv, acc.y * inv, acc.z * inv, acc.w * inv);

    if (!LAYER2) {
        float4 b4 = ((const float4*)bias)[lane];
        val.x = fmaxf(val.x + b4.x, 0.f);
        val.y = fmaxf(val.y + b4.y, 0.f);
        val.z = fmaxf(val.z + b4.z, 0.f);
        val.w = fmaxf(val.w + b4.w, 0.f);
        __half2 h0 = __floats2half2_rn(val.x, val.y);
        __half2 h1 = __floats2half2_rn(val.z, val.w);
        uint2 p; p.x = *(uint32_t*)&h0; p.y = *(uint32_t*)&h1;
        ((uint2*)OUT)[n * 32 + lane] = p;     // fp16 H1
    } else {
#pragma unroll
        for (int o = 8; o <= 16; o <<= 1) {
            val.x += __shfl_xor_sync(0xffffffffu, val.x, o);
            val.y += __shfl_xor_sync(0xffffffffu, val.y, o);
            val.z += __shfl_xor_sync(0xffffffffu, val.z, o);
            val.w += __shfl_xor_sync(0xffffffffu, val.w, o);
        }
        if (lane < 8) {
            float4 b4 = ((const float4*)bias)[lane];
            float4 o4 = make_float4(0.25f * val.x + b4.x, 0.25f * val.y + b4.y,
                                    0.25f * val.z + b4.z, 0.25f * val.w + b4.w);
            ((float4*)OUT)[n * 8 + lane] = o4;
        }
    }
}

// ---------------- global mean pool ----------------
__global__ void k_pool(const float* __restrict__ OUT2,
                       const int* __restrict__ batch, int N)
{
    int perBlock = (N + gridDim.x - 1) / gridDim.x;
    int n0 = blockIdx.x * perBlock;
    int n1 = min(N, n0 + perBlock);
    int ch  = threadIdx.x & 31;
    int sub = threadIdx.x >> 5;
    float sum = 0.f;
    int curb = -1;
    for (int n = n0 + sub; n < n1; n += 8) {
        int b = batch[n];
        if (b != curb) {
            if (curb >= 0) atomicAdd(&d_gsum[curb * 32 + ch], sum);
            curb = b; sum = 0.f;
        }
        sum += OUT2[n * 32 + ch];
    }
    if (curb >= 0) atomicAdd(&d_gsum[curb * 32 + ch], sum);
}

// ---------------- final MLP ----------------
__global__ void k_mlp(const int* __restrict__ batch, int N,
                      const float* __restrict__ stats,
                      const float* __restrict__ Wm1, const float* __restrict__ bm1,
                      const float* __restrict__ Wm2, const float* __restrict__ bm2,
                      float* __restrict__ out, int B)
{
    int g = threadIdx.x;
    if (g >= B) return;
    int lo0 = 0, hi0 = N;
    while (lo0 < hi0) { int mid = (lo0 + hi0) >> 1; if (batch[mid] < g) lo0 = mid + 1; else hi0 = mid; }
    int lo1 = lo0, hi1 = N;
    while (lo1 < hi1) { int mid = (lo1 + hi1) >> 1; if (batch[mid] < g + 1) lo1 = mid + 1; else hi1 = mid; }
    float cnt = (float)(lo1 - lo0);
    float inv = 1.f / fmaxf(cnt, 1.f);

    float v[47];
#pragma unroll
    for (int cc = 0; cc < 32; cc++) v[cc] = d_gsum[g * 32 + cc] * inv;
#pragma unroll
    for (int f = 0; f < 15; f++) v[32 + f] = stats[g * 15 + f];
    float o = bm2[0];
    for (int k = 0; k < 32; k++) {
        float hsum = bm1[k];
#pragma unroll
        for (int i = 0; i < 47; i++) hsum = fmaf(v[i], Wm1[i * 32 + k], hsum);
        o = fmaf(fmaxf(hsum, 0.f), Wm2[k], o);
    }
    out[g] = o;
}

// ---------------- launch ----------------
extern "C" void kernel_launch(void* const* d_in, const int* in_sizes, int n_in,
                              void* d_out, int out_size)
{
    const float* x     = (const float*)d_in[0];
    const int*   ei    = (const int*)d_in[1];
    const int*   batch = (const int*)d_in[2];
    const float* stats = (const float*)d_in[3];
    const float* W1    = (const float*)d_in[4];
    const float* as1   = (const float*)d_in[5];
    const float* ad1   = (const float*)d_in[6];
    const float* b1    = (const float*)d_in[7];
    const float* W2    = (const float*)d_in[8];
    const float* as2   = (const float*)d_in[9];
    const float* ad2   = (const float*)d_in[10];
    const float* b2    = (const float*)d_in[11];
    const float* Wm1   = (const float*)d_in[12];
    const float* bm1   = (const float*)d_in[13];
    const float* Wm2   = (const float*)d_in[14];
    const float* bm2   = (const float*)d_in[15];

    int N = in_sizes[0] / 128;
    int E = in_sizes[1] / 2;
    int B = in_sizes[3] / 15;

    __half *Wt1, *Wt2; __half2 *H1h; float *OUT2;
    cudaGetSymbolAddress((void**)&Wt1,  d_Wt1);
    cudaGetSymbolAddress((void**)&Wt2,  d_Wt2);
    cudaGetSymbolAddress((void**)&H1h,  d_H1h);
    cudaGetSymbolAddress((void**)&OUT2, d_OUT2);

    int gemmBlocks = (N + 127) / 128;
    int edgeBlocks = (E + 255) / 256;
    int fillBlocks = (E + N + 255) / 256;
    int aggBlocks  = (N + 3) / 4;
    int scanBlocks = (N + 1023) / 1024;

    k_init<<<64, 256>>>(N, B);
    k_prep<<<128, 256>>>(W1, W2);

    k_deg  <<<edgeBlocks, 256>>>(ei, E);
    k_scan1<<<scanBlocks, 1024>>>(N);
    k_scan2<<<1, 64>>>(scanBlocks);
    k_scan3<<<scanBlocks, 1024>>>(N);
    k_fill <<<fillBlocks, 256>>>(ei, E, N);

    k_gemm_att<false><<<gemmBlocks, 256>>>(x, Wt1, as1, ad1, N);
    k_agg<false><<<aggBlocks, 128>>>(b1, H1h, N);

    k_gemm_att<true><<<gemmBlocks, 256>>>(H1h, Wt2, as2, ad2, N);
    k_agg<true><<<aggBlocks, 128>>>(b2, OUT2, N);

    k_pool<<<128, 256>>>(OUT2, batch, N);
    k_mlp<<<1, 128>>>(batch, N, stats, Wm1, bm1, Wm2, bm2, (float*)d_out, B);
}